// round 1
// baseline (speedup 1.0000x reference)
#include <cuda_runtime.h>

#define BB 8
#define NN 2048
#define FF 256
#define M_TOT (BB*NN)   // 16384

// ---- scratch (device globals; no allocations allowed) ----
__device__ float g_h[M_TOT*FF];      // 16 MB: h = x @ W
__device__ float g_s1[M_TOT];
__device__ float g_s2[M_TOT];
__device__ float g_Zp[4*M_TOT];      // partial column sums
__device__ float g_invZ[M_TOT];

typedef unsigned long long ull;

__device__ __forceinline__ ull pack2(float x, float y){
    ull r; asm("mov.b64 %0, {%1,%2};" : "=l"(r) : "f"(x), "f"(y)); return r;
}
__device__ __forceinline__ void unpack2(ull v, float &x, float &y){
    asm("mov.b64 {%0,%1}, %2;" : "=f"(x), "=f"(y) : "l"(v));
}
// packed dual fp32 FMA (Blackwell f32x2 pipe)
__device__ __forceinline__ void ffma2(ull &d, ull a, ull b){
    asm("fma.rn.f32x2 %0, %1, %2, %0;" : "+l"(d) : "l"(a), "l"(b));
}

// ============================================================
// K1: h = x @ W   (16384 x 256 x 256), BM=128 BN=128 BK=16,
// 256 threads, 8x8 micro-tile via f32x2.
// ============================================================
__global__ __launch_bounds__(256,2) void gemm1_kernel(
    const float* __restrict__ x, const float* __restrict__ W)
{
    __shared__ float As[16][132];   // [k][m], padded
    __shared__ float Ws[16][128];   // [k][n]
    const int tid = threadIdx.x;
    const int tx = tid & 15, ty = tid >> 4;
    const int m0 = blockIdx.y * 128, n0 = blockIdx.x * 128;

    ull acc[8][4];
    #pragma unroll
    for (int i = 0; i < 8; i++)
        #pragma unroll
        for (int j = 0; j < 4; j++) acc[i][j] = 0ull;

    for (int kt = 0; kt < 256; kt += 16) {
        // load x tile (128 m x 16 k), transpose into As[k][m]
        #pragma unroll
        for (int p = 0; p < 2; p++) {
            int f = tid + p * 256;       // float4 index 0..511
            int m = f >> 2;
            int kb = (f & 3) * 4;
            float4 v = *(const float4*)&x[(size_t)(m0 + m) * 256 + kt + kb];
            As[kb+0][m] = v.x; As[kb+1][m] = v.y;
            As[kb+2][m] = v.z; As[kb+3][m] = v.w;
        }
        // load W tile (16 k x 128 n)
        #pragma unroll
        for (int p = 0; p < 2; p++) {
            int f = tid + p * 256;       // 0..511
            int k = f >> 5, q = f & 31;
            *(float4*)&Ws[k][q*4] = *(const float4*)&W[(size_t)(kt + k) * 256 + n0 + q*4];
        }
        __syncthreads();
        #pragma unroll
        for (int k = 0; k < 16; k++) {
            float4 aL = *(const float4*)&As[k][ty*4];
            float4 aH = *(const float4*)&As[k][64 + ty*4];
            ull b0 = *(const ull*)&Ws[k][tx*4];
            ull b1 = *(const ull*)&Ws[k][tx*4 + 2];
            ull b2 = *(const ull*)&Ws[k][64 + tx*4];
            ull b3 = *(const ull*)&Ws[k][64 + tx*4 + 2];
            float am[8] = {aL.x, aL.y, aL.z, aL.w, aH.x, aH.y, aH.z, aH.w};
            #pragma unroll
            for (int mi = 0; mi < 8; mi++) {
                ull a2 = pack2(am[mi], am[mi]);
                ffma2(acc[mi][0], a2, b0);
                ffma2(acc[mi][1], a2, b1);
                ffma2(acc[mi][2], a2, b2);
                ffma2(acc[mi][3], a2, b3);
            }
        }
        __syncthreads();
    }
    // epilogue: m = m0 + (mi<4 ? ty*4+mi : 64+ty*4+(mi-4)); n = n0 + tx*4 (+64)
    #pragma unroll
    for (int mi = 0; mi < 8; mi++) {
        int m = m0 + ((mi < 4) ? (ty*4 + mi) : (64 + ty*4 + (mi - 4)));
        float4 o0, o1;
        unpack2(acc[mi][0], o0.x, o0.y); unpack2(acc[mi][1], o0.z, o0.w);
        unpack2(acc[mi][2], o1.x, o1.y); unpack2(acc[mi][3], o1.z, o1.w);
        *(float4*)&g_h[(size_t)m * 256 + n0 + tx*4]      = o0;
        *(float4*)&g_h[(size_t)m * 256 + n0 + 64 + tx*4] = o1;
    }
}

// ============================================================
// K2: s1[r] = h[r,:] . a1 ; s2[r] = h[r,:] . a2  (one warp/row)
// ============================================================
__global__ void s_kernel(const float* __restrict__ a)
{
    int warp = threadIdx.x >> 5, lane = threadIdx.x & 31;
    int row = blockIdx.x * 8 + warp;
    const float* hr = &g_h[(size_t)row * 256];
    float s1 = 0.f, s2 = 0.f;
    #pragma unroll
    for (int q = 0; q < 8; q++) {
        int e = lane + 32 * q;
        float v = hr[e];
        s1 += v * __ldg(&a[e]);
        s2 += v * __ldg(&a[256 + e]);
    }
    #pragma unroll
    for (int o = 16; o > 0; o >>= 1) {
        s1 += __shfl_xor_sync(0xffffffffu, s1, o);
        s2 += __shfl_xor_sync(0xffffffffu, s2, o);
    }
    if (lane == 0) { g_s1[row] = s1; g_s2[row] = s2; }
}

// ============================================================
// K3: partial column sums Z[b,j] = sum_i adj * exp(lrelu(s1_i+s2_j))
// grid (8 jtiles, 4 isegs, 8 b), 256 threads; coalesced adj rows.
// ============================================================
__global__ void zpart_kernel(const int* __restrict__ adj)
{
    int b   = blockIdx.z;
    int seg = blockIdx.y;
    int j   = blockIdx.x * 256 + threadIdx.x;
    float s2j = g_s2[b * NN + j];
    const int*   ap  = adj + (size_t)b * NN * NN + j;
    const float* s1p = &g_s1[b * NN];
    float z = 0.f;
    int i0 = seg * 512;
    #pragma unroll 4
    for (int i = i0; i < i0 + 512; i++) {
        int av = __ldg(&ap[(size_t)i * NN]);
        float v = __ldg(&s1p[i]) + s2j;
        v = v > 0.f ? v : 0.2f * v;
        float e = __expf(v);
        z += (av > 0) ? e : 0.f;
    }
    g_Zp[(size_t)seg * M_TOT + b * NN + j] = z;
}

__global__ void zreduce_kernel()
{
    int idx = blockIdx.x * 256 + threadIdx.x;
    float z = g_Zp[idx] + g_Zp[M_TOT + idx] + g_Zp[2*M_TOT + idx] + g_Zp[3*M_TOT + idx];
    g_invZ[idx] = 1.0f / z;
}

// ============================================================
// K5: h'[b,i,o] = sum_j w[b,i,j] * h[b,j,o];  out = elu(h')
// w computed on the fly: adj ? exp(lrelu(s1+s2))*invZ[j] : 0
// Block: b x 64-row i-tile, all 256 o. BJ=32 chunks.
// 256 threads, 8i x 8o micro-tile via f32x2.
// ============================================================
__global__ __launch_bounds__(256,2) void attgemm_kernel(
    const int* __restrict__ adj, float* __restrict__ out)
{
    __shared__ float hs[32][256];     // h chunk [jj][o]
    __shared__ float ws[64][32];      // weights [ii][jj]
    __shared__ float s1s[64];

    const int tid  = threadIdx.x;
    const int lane = tid & 31;
    const int wrp  = tid >> 5;
    const int b    = blockIdx.y;
    const int i0   = blockIdx.x * 64;

    if (tid < 64) s1s[tid] = g_s1[b * NN + i0 + tid];

    ull acc[8][4];
    #pragma unroll
    for (int r = 0; r < 8; r++)
        #pragma unroll
        for (int p = 0; p < 4; p++) acc[r][p] = 0ull;

    __syncthreads();

    for (int j0 = 0; j0 < NN; j0 += 32) {
        // --- phase A: stage h[b, j0..j0+31, :] ---
        #pragma unroll
        for (int q = 0; q < 8; q++) {
            int p   = tid + q * 256;       // float4 index 0..2047
            int row = p >> 6, c4 = p & 63;
            *(float4*)&hs[row][c4 * 4] =
                *(const float4*)&g_h[(size_t)(b * NN + j0 + row) * 256 + c4 * 4];
        }
        // --- phase B: weights tile 64 x 32 ---
        float s2v = __ldg(&g_s2[b * NN + j0 + lane]);
        float izv = __ldg(&g_invZ[b * NN + j0 + lane]);
        #pragma unroll
        for (int q = 0; q < 8; q++) {
            int ii = wrp + q * 8;          // 0..63
            int av = __ldg(&adj[(size_t)(b * NN + i0 + ii) * NN + j0 + lane]);
            float v = s1s[ii] + s2v;
            v = v > 0.f ? v : 0.2f * v;
            float e = __expf(v) * izv;
            ws[ii][lane] = (av > 0) ? e : 0.f;
        }
        __syncthreads();
        // --- phase C: rank-32 update ---
        #pragma unroll
        for (int jj = 0; jj < 32; jj++) {
            ull h0 = *(const ull*)&hs[jj][lane * 4];
            ull h1 = *(const ull*)&hs[jj][lane * 4 + 2];
            ull h2 = *(const ull*)&hs[jj][128 + lane * 4];
            ull h3 = *(const ull*)&hs[jj][128 + lane * 4 + 2];
            #pragma unroll
            for (int r = 0; r < 8; r++) {
                float w = ws[wrp * 8 + r][jj];   // broadcast
                ull w2 = pack2(w, w);
                ffma2(acc[r][0], w2, h0);
                ffma2(acc[r][1], w2, h1);
                ffma2(acc[r][2], w2, h2);
                ffma2(acc[r][3], w2, h3);
            }
        }
        __syncthreads();
    }

    // --- epilogue: ELU + store ---
    #pragma unroll
    for (int r = 0; r < 8; r++) {
        int i = i0 + wrp * 8 + r;
        float f[8];
        unpack2(acc[r][0], f[0], f[1]); unpack2(acc[r][1], f[2], f[3]);
        unpack2(acc[r][2], f[4], f[5]); unpack2(acc[r][3], f[6], f[7]);
        #pragma unroll
        for (int c = 0; c < 8; c++) f[c] = (f[c] > 0.f) ? f[c] : expm1f(f[c]);
        float4 o0 = make_float4(f[0], f[1], f[2], f[3]);
        float4 o1 = make_float4(f[4], f[5], f[6], f[7]);
        size_t base = (size_t)(b * NN + i) * 256;
        *(float4*)&out[base + lane * 4]       = o0;
        *(float4*)&out[base + 128 + lane * 4] = o1;
    }
}

extern "C" void kernel_launch(void* const* d_in, const int* in_sizes, int n_in,
                              void* d_out, int out_size)
{
    const float* x   = (const float*)d_in[0];
    const int*   adj = (const int*)d_in[1];
    const float* W   = (const float*)d_in[2];
    const float* a   = (const float*)d_in[3];
    float* out = (float*)d_out;

    gemm1_kernel<<<dim3(2, 128), 256>>>(x, W);
    s_kernel<<<2048, 256>>>(a);
    zpart_kernel<<<dim3(8, 4, 8), 256>>>(adj);
    zreduce_kernel<<<64, 256>>>();
    attgemm_kernel<<<dim3(32, 8), 256>>>(adj, out);
}

// round 3
// speedup vs baseline: 1.8884x; 1.8884x over previous
#include <cuda_runtime.h>
#include <cuda_bf16.h>

typedef unsigned int uint32;

#define BB 8
#define NN 2048
#define FF 256
#define M_TOT (BB*NN)   // 16384
#define PITCH 80        // bytes per 32-bf16 row in SMEM tiles (conflict-free for ldmatrix)

// ---- scratch (device globals; no runtime allocations) ----
__device__ __align__(16) float g_h[M_TOT*FF];              // 16 MB fp32 h
__device__ float g_s1[M_TOT], g_s2[M_TOT];
__device__ float g_E1[M_TOT], g_E1p[M_TOT], g_E2[M_TOT], g_E2p[M_TOT];
__device__ float g_Zp[8*M_TOT];
__device__ float g_invZ[M_TOT];
__device__ __align__(16) unsigned int g_hTh[M_TOT*FF/2];   // h^T bf16 hi, [b][o][j-pairs]
__device__ __align__(16) unsigned int g_hTl[M_TOT*FF/2];   // h^T bf16 lo
__device__ __align__(16) unsigned int g_xh[M_TOT*FF/2];    // x bf16 hi, [m][k-pairs]
__device__ __align__(16) unsigned int g_xl[M_TOT*FF/2];
__device__ __align__(16) unsigned int g_WTh[FF*FF/2];      // W^T bf16 hi, [n][k-pairs]
__device__ __align__(16) unsigned int g_WTl[FF*FF/2];

// ================= helpers =================
__device__ __forceinline__ uint32 smem_u32(const void* p){
    uint32 a; asm("{ .reg .u64 t; cvta.to.shared.u64 t, %1; cvt.u32.u64 %0, t; }" : "=r"(a) : "l"(p));
    return a;
}
// pack two fp32 -> bf16x2 (a -> low half, b -> high half)
__device__ __forceinline__ uint32 pack_bf2(float a, float b){
    uint32 r; asm("cvt.rn.bf16x2.f32 %0, %1, %2;" : "=r"(r) : "f"(b), "f"(a)); return r;
}
__device__ __forceinline__ void sts32(uint32 addr, uint32 v){
    asm volatile("st.shared.b32 [%0], %1;" :: "r"(addr), "r"(v) : "memory");
}
__device__ __forceinline__ void sts128(uint32 addr, uint4 v){
    asm volatile("st.shared.v4.b32 [%0], {%1,%2,%3,%4};"
        :: "r"(addr), "r"(v.x), "r"(v.y), "r"(v.z), "r"(v.w) : "memory");
}
__device__ __forceinline__ void ldm4(uint32* r, uint32 addr){
    asm volatile("ldmatrix.sync.aligned.m8n8.x4.shared.b16 {%0,%1,%2,%3}, [%4];"
        : "=r"(r[0]), "=r"(r[1]), "=r"(r[2]), "=r"(r[3]) : "r"(addr));
}
__device__ __forceinline__ void mma_bf16(float* c, const uint32* a, uint32 b0, uint32 b1){
    asm volatile("mma.sync.aligned.m16n8k16.row.col.f32.bf16.bf16.f32 "
        "{%0,%1,%2,%3}, {%4,%5,%6,%7}, {%8,%9}, {%0,%1,%2,%3};"
        : "+f"(c[0]), "+f"(c[1]), "+f"(c[2]), "+f"(c[3])
        : "r"(a[0]), "r"(a[1]), "r"(a[2]), "r"(a[3]), "r"(b0), "r"(b1));
}

// split fp32 pair -> bf16x2 hi + bf16x2 lo
__device__ __forceinline__ void split_pair(float v0, float v1, uint32& hi, uint32& lo){
    hi = pack_bf2(v0, v1);
    float l0 = v0 - __uint_as_float(hi << 16);
    float l1 = v1 - __uint_as_float(hi & 0xFFFF0000u);
    lo = pack_bf2(l0, l1);
}

// ---- shared MMA core: one 32-wide K chunk, warp tile 32(i) x 64(o) ----
// tiles: rows x 32 bf16 (PITCH bytes per row). 3 split passes: AhBh + AhBl + AlBh.
__device__ __forceinline__ void mma_chunk(float c[2][8][4],
    uint32 Ah, uint32 Al, uint32 Bh, uint32 Bl, int iw, int ow, int lane)
{
    const uint32 lr = (lane & 7) + ((lane >> 3) & 1) * 8;
    const uint32 lc = (lane >> 4) * 16;
    #pragma unroll
    for (int ks = 0; ks < 2; ks++) {
        const uint32 off = lr * PITCH + lc + ks * 32;
        uint32 A0[4], A1[4], BH[4][4], BL[4][4];
        ldm4(A0, Ah + (uint32)(iw)      * PITCH + off);
        ldm4(A1, Ah + (uint32)(iw + 16) * PITCH + off);
        #pragma unroll
        for (int t = 0; t < 4; t++) ldm4(BH[t], Bh + (uint32)(ow + t*16) * PITCH + off);
        #pragma unroll
        for (int t = 0; t < 4; t++) {
            mma_bf16(c[0][t*2+0], A0, BH[t][0], BH[t][2]);
            mma_bf16(c[1][t*2+0], A1, BH[t][0], BH[t][2]);
            mma_bf16(c[0][t*2+1], A0, BH[t][1], BH[t][3]);
            mma_bf16(c[1][t*2+1], A1, BH[t][1], BH[t][3]);
        }
        #pragma unroll
        for (int t = 0; t < 4; t++) ldm4(BL[t], Bl + (uint32)(ow + t*16) * PITCH + off);
        #pragma unroll
        for (int t = 0; t < 4; t++) {
            mma_bf16(c[0][t*2+0], A0, BL[t][0], BL[t][2]);
            mma_bf16(c[1][t*2+0], A1, BL[t][0], BL[t][2]);
            mma_bf16(c[0][t*2+1], A0, BL[t][1], BL[t][3]);
            mma_bf16(c[1][t*2+1], A1, BL[t][1], BL[t][3]);
        }
        ldm4(A0, Al + (uint32)(iw)      * PITCH + off);
        ldm4(A1, Al + (uint32)(iw + 16) * PITCH + off);
        #pragma unroll
        for (int t = 0; t < 4; t++) {
            mma_bf16(c[0][t*2+0], A0, BH[t][0], BH[t][2]);
            mma_bf16(c[1][t*2+0], A1, BH[t][0], BH[t][2]);
            mma_bf16(c[0][t*2+1], A0, BH[t][1], BH[t][3]);
            mma_bf16(c[1][t*2+1], A1, BH[t][1], BH[t][3]);
        }
    }
}

// ============================================================
// xsplit: x fp32 -> bf16 hi/lo pairs [m][k/2]
// ============================================================
__global__ void xsplit_kernel(const float* __restrict__ x)
{
    int idx = blockIdx.x * 256 + threadIdx.x;
    #pragma unroll
    for (int r = 0; r < 8; r++) {
        int p = idx + r * 262144;    // 2,097,152 pairs total
        float2 v = ((const float2*)x)[p];
        uint32 hi, lo; split_pair(v.x, v.y, hi, lo);
        g_xh[p] = hi; g_xl[p] = lo;
    }
}

// ============================================================
// wsplitT: W [k][n] fp32 -> W^T bf16 hi/lo [n][k/2]
// ============================================================
__global__ void wsplitT_kernel(const float* __restrict__ W)
{
    int idx = blockIdx.x * 256 + threadIdx.x;   // 32768 pairs
    int n = idx >> 7, kp = idx & 127;
    float v0 = W[(size_t)(2*kp)   * FF + n];
    float v1 = W[(size_t)(2*kp+1) * FF + n];
    uint32 hi, lo; split_pair(v0, v1, hi, lo);
    g_WTh[n*128 + kp] = hi; g_WTl[n*128 + kp] = lo;
}

// ============================================================
// gemm1: h = x @ W  via bf16 HMMA 3-pass. grid (2 ntile, 128 mtile)
// ============================================================
__global__ __launch_bounds__(256,2) void gemm1_mma(void)
{
    __shared__ __align__(16) unsigned char smA[2][128*PITCH];
    __shared__ __align__(16) unsigned char smB[2][128*PITCH];
    const uint32 Ah = smem_u32(smA[0]), Al = smem_u32(smA[1]);
    const uint32 Bh = smem_u32(smB[0]), Bl = smem_u32(smB[1]);
    const int tid = threadIdx.x, lane = tid & 31, wid = tid >> 5;
    const int m0 = blockIdx.y * 128, n0 = blockIdx.x * 128;
    const int iw = (wid & 3) * 32, ow = (wid >> 2) * 64;

    float c[2][8][4];
    #pragma unroll
    for (int a = 0; a < 2; a++)
        #pragma unroll
        for (int b_ = 0; b_ < 8; b_++)
            #pragma unroll
            for (int d = 0; d < 4; d++) c[a][b_][d] = 0.f;

    const uint4* xh = (const uint4*)g_xh;  const uint4* xl = (const uint4*)g_xl;
    const uint4* wh = (const uint4*)g_WTh; const uint4* wl = (const uint4*)g_WTl;

    for (int kt = 0; kt < 256; kt += 32) {
        __syncthreads();
        #pragma unroll
        for (int p = 0; p < 2; p++) {
            int q = tid + p * 256;
            int row = q >> 2, seg = q & 3;
            uint32 off = (uint32)row * PITCH + seg * 16;
            size_t giA = (size_t)(m0 + row) * 32 + (kt >> 3) + seg;
            size_t giB = (size_t)(n0 + row) * 32 + (kt >> 3) + seg;
            sts128(Ah + off, xh[giA]);
            sts128(Al + off, xl[giA]);
            sts128(Bh + off, wh[giB]);
            sts128(Bl + off, wl[giB]);
        }
        __syncthreads();
        mma_chunk(c, Ah, Al, Bh, Bl, iw, ow, lane);
    }

    const int g = lane >> 2, cq = (lane & 3) * 2;
    #pragma unroll
    for (int mt = 0; mt < 2; mt++)
        #pragma unroll
        for (int nt = 0; nt < 8; nt++) {
            int m = m0 + iw + mt*16 + g;
            int o = n0 + ow + nt*8 + cq;
            *(float2*)&g_h[(size_t)m * FF + o]       = make_float2(c[mt][nt][0], c[mt][nt][1]);
            *(float2*)&g_h[(size_t)(m+8) * FF + o]   = make_float2(c[mt][nt][2], c[mt][nt][3]);
        }
}

// ============================================================
// s_kernel: s1/s2 row dots + exp tables
// ============================================================
__global__ void s_kernel(const float* __restrict__ a)
{
    int warp = threadIdx.x >> 5, lane = threadIdx.x & 31;
    int row = blockIdx.x * 8 + warp;
    const float* hr = &g_h[(size_t)row * 256];
    float s1 = 0.f, s2 = 0.f;
    #pragma unroll
    for (int q = 0; q < 8; q++) {
        int e = lane + 32 * q;
        float v = hr[e];
        s1 += v * __ldg(&a[e]);
        s2 += v * __ldg(&a[256 + e]);
    }
    #pragma unroll
    for (int o = 16; o > 0; o >>= 1) {
        s1 += __shfl_xor_sync(0xffffffffu, s1, o);
        s2 += __shfl_xor_sync(0xffffffffu, s2, o);
    }
    if (lane == 0) {
        g_s1[row] = s1; g_s2[row] = s2;
        g_E1[row]  = __expf(s1);        g_E2[row]  = __expf(s2);
        g_E1p[row] = __expf(0.2f * s1); g_E2p[row] = __expf(0.2f * s2);
    }
}

// ============================================================
// hsplit: transpose + bf16 hi/lo split of h -> g_hTh/g_hTl [b][o][j]
// ============================================================
__global__ void hsplit_kernel()
{
    __shared__ float t[64][33];
    const int b = blockIdx.z, j0 = blockIdx.x * 64, o0 = blockIdx.y * 32;
    const int tid = threadIdx.x;
    const int o = tid & 31, jr = tid >> 5;
    #pragma unroll
    for (int r = 0; r < 8; r++)
        t[jr + r*8][o] = g_h[((size_t)(b*NN + j0 + jr + r*8))*FF + o0 + o];
    __syncthreads();
    const int jl = (tid & 31) * 2, ob = tid >> 5;
    #pragma unroll
    for (int r = 0; r < 4; r++) {
        int oo = ob + r*8;
        uint32 hi, lo; split_pair(t[jl][oo], t[jl+1][oo], hi, lo);
        size_t pi = ((size_t)(b*FF + o0 + oo)) * (NN/2) + (j0 + jl)/2;
        g_hTh[pi] = hi;
        g_hTl[pi] = lo;
    }
}

// ============================================================
// zpass: Z[b,j] = sum_i adj * max(E1_i*E2_j, E1p_i*E2p_j)  (no exp!)
// grid (4 jchunk, 8 iseg, 8 b), 256 thr, 2 j per thread
// ============================================================
__global__ __launch_bounds__(256) void zpass_kernel(const int* __restrict__ adj)
{
    __shared__ float sE1[256], sE1p[256];
    const int b = blockIdx.z, iseg = blockIdx.y;
    const int tid = threadIdx.x;
    const int j = blockIdx.x * 512 + tid * 2;
    const int ibase = iseg * 256;
    sE1[tid]  = g_E1[b*NN + ibase + tid];
    sE1p[tid] = g_E1p[b*NN + ibase + tid];
    __syncthreads();
    float e20 = __ldg(&g_E2[b*NN + j]),  e21 = __ldg(&g_E2[b*NN + j + 1]);
    float ep0 = __ldg(&g_E2p[b*NN + j]), ep1 = __ldg(&g_E2p[b*NN + j + 1]);
    const int2* ap = (const int2*)(adj + (size_t)(b*NN + ibase) * NN) + (j >> 1);
    float z0 = 0.f, z1 = 0.f;
    #pragma unroll 4
    for (int il = 0; il < 256; il++) {
        int2 av = __ldg(&ap[(size_t)il * (NN/2)]);
        float E1v = sE1[il], E1pv = sE1p[il];
        float q0 = fmaxf(E1v * e20, E1pv * ep0);
        float q1 = fmaxf(E1v * e21, E1pv * ep1);
        z0 = fmaf(q0, __int_as_float(av.x * 0x3f800000), z0);
        z1 = fmaf(q1, __int_as_float(av.y * 0x3f800000), z1);
    }
    g_Zp[(size_t)iseg * M_TOT + b*NN + j]     = z0;
    g_Zp[(size_t)iseg * M_TOT + b*NN + j + 1] = z1;
}

__global__ void zreduce_kernel()
{
    int idx = blockIdx.x * 256 + threadIdx.x;
    float z = 0.f;
    #pragma unroll
    for (int s = 0; s < 8; s++) z += g_Zp[(size_t)s * M_TOT + idx];
    g_invZ[idx] = 1.0f / z;
}

// ============================================================
// attgemm: h'[i,o] = sum_j w[i,j] h[j,o], ELU epilogue.
// w generated on the fly into SMEM bf16 hi/lo; HMMA 3-pass.
// grid (16 itile, 2 otile, 8 b), 256 thr.
// ============================================================
__global__ __launch_bounds__(256,2) void attgemm_mma(
    const int* __restrict__ adj, float* __restrict__ out)
{
    __shared__ float sE1[128], sE1p[128];
    __shared__ __align__(16) unsigned char smA[2][128*PITCH];
    __shared__ __align__(16) unsigned char smB[2][128*PITCH];
    const uint32 Ah = smem_u32(smA[0]), Al = smem_u32(smA[1]);
    const uint32 Bh = smem_u32(smB[0]), Bl = smem_u32(smB[1]);
    const int tid = threadIdx.x, lane = tid & 31, wid = tid >> 5;
    const int b  = blockIdx.z;
    const int i0 = blockIdx.x * 128, o0 = blockIdx.y * 128;
    const int iw = (wid & 3) * 32, ow = (wid >> 2) * 64;

    if (tid < 128) {
        sE1[tid]  = g_E1[b*NN + i0 + tid];
        sE1p[tid] = g_E1p[b*NN + i0 + tid];
    }

    float c[2][8][4];
    #pragma unroll
    for (int x = 0; x < 2; x++)
        #pragma unroll
        for (int y = 0; y < 8; y++)
            #pragma unroll
            for (int d = 0; d < 4; d++) c[x][y][d] = 0.f;

    const uint4* srcH = (const uint4*)g_hTh;
    const uint4* srcL = (const uint4*)g_hTl;
    const int2* arow = (const int2*)(adj + (size_t)(b*NN + i0) * NN);
    const float* E2b  = &g_E2[b*NN];
    const float* E2pb = &g_E2p[b*NN];
    const float* IZb  = &g_invZ[b*NN];

    for (int j0 = 0; j0 < NN; j0 += 32) {
        __syncthreads();
        // ---- A tile: attention weights 128 x 32, bf16 hi/lo ----
        #pragma unroll
        for (int r = 0; r < 8; r++) {
            int pp = tid + r * 256;
            int i = pp >> 4, jp = pp & 15;
            int jg = j0 + jp * 2;
            int2 av = __ldg(&arow[(size_t)i * (NN/2) + (jg >> 1)]);
            float E1v = sE1[i], E1pv = sE1p[i];
            float q0 = fmaxf(E1v * __ldg(&E2b[jg]),   E1pv * __ldg(&E2pb[jg]));
            float q1 = fmaxf(E1v * __ldg(&E2b[jg+1]), E1pv * __ldg(&E2pb[jg+1]));
            float w0 = av.x ? q0 * __ldg(&IZb[jg])   : 0.f;
            float w1 = av.y ? q1 * __ldg(&IZb[jg+1]) : 0.f;
            uint32 hi, lo; split_pair(w0, w1, hi, lo);
            uint32 off = (uint32)i * PITCH + jp * 4;
            sts32(Ah + off, hi);
            sts32(Al + off, lo);
        }
        // ---- B tile: hT[b, o0..o0+127, j0..j0+31] ----
        #pragma unroll
        for (int p = 0; p < 2; p++) {
            int q = tid + p * 256;
            int o = q >> 2, seg = q & 3;
            size_t gi = ((size_t)(b*FF + o0 + o)) * 256 + (j0 >> 3) + seg;
            uint32 off = (uint32)o * PITCH + seg * 16;
            sts128(Bh + off, srcH[gi]);
            sts128(Bl + off, srcL[gi]);
        }
        __syncthreads();
        mma_chunk(c, Ah, Al, Bh, Bl, iw, ow, lane);
    }

    // ---- epilogue: ELU + store ----
    const int g = lane >> 2, cq = (lane & 3) * 2;
    #pragma unroll
    for (int mt = 0; mt < 2; mt++)
        #pragma unroll
        for (int nt = 0; nt < 8; nt++) {
            int i = i0 + iw + mt*16 + g;
            int o = o0 + ow + nt*8 + cq;
            float f0 = c[mt][nt][0], f1 = c[mt][nt][1];
            float f2 = c[mt][nt][2], f3 = c[mt][nt][3];
            f0 = f0 > 0.f ? f0 : expm1f(f0);
            f1 = f1 > 0.f ? f1 : expm1f(f1);
            f2 = f2 > 0.f ? f2 : expm1f(f2);
            f3 = f3 > 0.f ? f3 : expm1f(f3);
            *(float2*)&out[((size_t)(b*NN + i))   * FF + o] = make_float2(f0, f1);
            *(float2*)&out[((size_t)(b*NN + i+8)) * FF + o] = make_float2(f2, f3);
        }
}

extern "C" void kernel_launch(void* const* d_in, const int* in_sizes, int n_in,
                              void* d_out, int out_size)
{
    const float* x   = (const float*)d_in[0];
    const int*   adj = (const int*)d_in[1];
    const float* W   = (const float*)d_in[2];
    const float* a   = (const float*)d_in[3];
    float* out = (float*)d_out;

    xsplit_kernel<<<1024, 256>>>(x);
    wsplitT_kernel<<<128, 256>>>(W);
    gemm1_mma<<<dim3(2, 128), 256>>>();
    s_kernel<<<2048, 256>>>(a);
    hsplit_kernel<<<dim3(32, 8, 8), 256>>>();
    zpass_kernel<<<dim3(4, 8, 8), 256>>>(adj);
    zreduce_kernel<<<64, 256>>>();
    attgemm_mma<<<dim3(16, 2, 8), 256>>>(adj, out);
}

// round 4
// speedup vs baseline: 1.9810x; 1.0491x over previous
#include <cuda_runtime.h>
#include <cuda_bf16.h>

typedef unsigned int uint32;

#define BB 8
#define NN 2048
#define FF 256
#define M_TOT (BB*NN)   // 16384
#define PITCH 80        // bytes per 32-bf16 row in SMEM tiles (conflict-free ldmatrix)

// ---- scratch (device globals; no runtime allocations) ----
__device__ __align__(16) float g_h[M_TOT*FF];              // 16 MB fp32 h
__device__ float g_s1[M_TOT], g_s2[M_TOT];
__device__ float g_E1[M_TOT], g_E1p[M_TOT], g_E2[M_TOT], g_E2p[M_TOT];
__device__ __align__(16) float g_Zp[8*M_TOT];
__device__ __align__(16) float2 g_u2[M_TOT];               // (E2*invZ, E2p*invZ)
__device__ __align__(16) unsigned int g_hTh[M_TOT*FF/2];   // h^T bf16 hi, [b][o][j-pairs]
__device__ __align__(16) unsigned int g_hTl[M_TOT*FF/2];   // h^T bf16 lo
__device__ __align__(16) unsigned int g_xh[M_TOT*FF/2];    // x bf16 hi, [m][k-pairs]
__device__ __align__(16) unsigned int g_xl[M_TOT*FF/2];
__device__ __align__(16) unsigned int g_WTh[FF*FF/2];      // W^T bf16 hi, [n][k-pairs]
__device__ __align__(16) unsigned int g_WTl[FF*FF/2];

// ================= helpers =================
__device__ __forceinline__ uint32 smem_u32(const void* p){
    uint32 a; asm("{ .reg .u64 t; cvta.to.shared.u64 t, %1; cvt.u32.u64 %0, t; }" : "=r"(a) : "l"(p));
    return a;
}
__device__ __forceinline__ uint32 pack_bf2(float a, float b){
    uint32 r; asm("cvt.rn.bf16x2.f32 %0, %1, %2;" : "=r"(r) : "f"(b), "f"(a)); return r;
}
__device__ __forceinline__ void sts32(uint32 addr, uint32 v){
    asm volatile("st.shared.b32 [%0], %1;" :: "r"(addr), "r"(v) : "memory");
}
__device__ __forceinline__ void sts128(uint32 addr, uint4 v){
    asm volatile("st.shared.v4.b32 [%0], {%1,%2,%3,%4};"
        :: "r"(addr), "r"(v.x), "r"(v.y), "r"(v.z), "r"(v.w) : "memory");
}
__device__ __forceinline__ void ldm4(uint32* r, uint32 addr){
    asm volatile("ldmatrix.sync.aligned.m8n8.x4.shared.b16 {%0,%1,%2,%3}, [%4];"
        : "=r"(r[0]), "=r"(r[1]), "=r"(r[2]), "=r"(r[3]) : "r"(addr));
}
__device__ __forceinline__ void mma_bf16(float* c, const uint32* a, uint32 b0, uint32 b1){
    asm volatile("mma.sync.aligned.m16n8k16.row.col.f32.bf16.bf16.f32 "
        "{%0,%1,%2,%3}, {%4,%5,%6,%7}, {%8,%9}, {%0,%1,%2,%3};"
        : "+f"(c[0]), "+f"(c[1]), "+f"(c[2]), "+f"(c[3])
        : "r"(a[0]), "r"(a[1]), "r"(a[2]), "r"(a[3]), "r"(b0), "r"(b1));
}
__device__ __forceinline__ void cpa16(uint32 dst, const void* src){
    asm volatile("cp.async.cg.shared.global [%0], [%1], 16;" :: "r"(dst), "l"(src) : "memory");
}
#define CPA_COMMIT() asm volatile("cp.async.commit_group;" ::: "memory")
#define CPA_WAIT0()  asm volatile("cp.async.wait_group 0;" ::: "memory")

__device__ __forceinline__ void split_pair(float v0, float v1, uint32& hi, uint32& lo){
    hi = pack_bf2(v0, v1);
    float l0 = v0 - __uint_as_float(hi << 16);
    float l1 = v1 - __uint_as_float(hi & 0xFFFF0000u);
    lo = pack_bf2(l0, l1);
}

// ---- MMA core: one 32-wide K chunk, warp tile 32(i) x 64(o), 3-pass hi/lo ----
__device__ __forceinline__ void mma_chunk(float c[2][8][4],
    uint32 Ah, uint32 Al, uint32 Bh, uint32 Bl, int iw, int ow, int lane)
{
    const uint32 base_off = (uint32)(lane & 15) * PITCH + (uint32)(lane >> 4) * 16;
    #pragma unroll
    for (int ks = 0; ks < 2; ks++) {
        const uint32 off = base_off + ks * 32;
        uint32 A0[4], A1[4], A0l[4], A1l[4], B[4][4];
        ldm4(A0, Ah + (uint32)iw * PITCH + off);
        ldm4(A1, Ah + (uint32)(iw + 16) * PITCH + off);
        #pragma unroll
        for (int t = 0; t < 4; t++) ldm4(B[t], Bh + (uint32)(ow + t*16) * PITCH + off);
        #pragma unroll
        for (int t = 0; t < 4; t++) {
            mma_bf16(c[0][t*2+0], A0, B[t][0], B[t][2]);
            mma_bf16(c[1][t*2+0], A1, B[t][0], B[t][2]);
            mma_bf16(c[0][t*2+1], A0, B[t][1], B[t][3]);
            mma_bf16(c[1][t*2+1], A1, B[t][1], B[t][3]);
        }
        ldm4(A0l, Al + (uint32)iw * PITCH + off);
        ldm4(A1l, Al + (uint32)(iw + 16) * PITCH + off);
        #pragma unroll
        for (int t = 0; t < 4; t++) {
            mma_bf16(c[0][t*2+0], A0l, B[t][0], B[t][2]);
            mma_bf16(c[1][t*2+0], A1l, B[t][0], B[t][2]);
            mma_bf16(c[0][t*2+1], A0l, B[t][1], B[t][3]);
            mma_bf16(c[1][t*2+1], A1l, B[t][1], B[t][3]);
        }
        #pragma unroll
        for (int t = 0; t < 4; t++) ldm4(B[t], Bl + (uint32)(ow + t*16) * PITCH + off);
        #pragma unroll
        for (int t = 0; t < 4; t++) {
            mma_bf16(c[0][t*2+0], A0, B[t][0], B[t][2]);
            mma_bf16(c[1][t*2+0], A1, B[t][0], B[t][2]);
            mma_bf16(c[0][t*2+1], A0, B[t][1], B[t][3]);
            mma_bf16(c[1][t*2+1], A1, B[t][1], B[t][3]);
        }
    }
}

// ============================================================
// xsplit: x fp32 -> bf16 hi/lo pairs [m][k/2]
// ============================================================
__global__ void xsplit_kernel(const float* __restrict__ x)
{
    int idx = blockIdx.x * 256 + threadIdx.x;
    #pragma unroll
    for (int r = 0; r < 8; r++) {
        int p = idx + r * 262144;
        float2 v = ((const float2*)x)[p];
        uint32 hi, lo; split_pair(v.x, v.y, hi, lo);
        g_xh[p] = hi; g_xl[p] = lo;
    }
}

// ============================================================
// wsplitT: W [k][n] fp32 -> W^T bf16 hi/lo [n][k/2]
// ============================================================
__global__ void wsplitT_kernel(const float* __restrict__ W)
{
    int idx = blockIdx.x * 256 + threadIdx.x;
    int n = idx >> 7, kp = idx & 127;
    float v0 = W[(size_t)(2*kp)   * FF + n];
    float v1 = W[(size_t)(2*kp+1) * FF + n];
    uint32 hi, lo; split_pair(v0, v1, hi, lo);
    g_WTh[n*128 + kp] = hi; g_WTl[n*128 + kp] = lo;
}

// ============================================================
// gemm1: h = x @ W  via bf16 HMMA 3-pass. grid (2 ntile, 128 mtile)
// ============================================================
__global__ __launch_bounds__(256,2) void gemm1_mma(void)
{
    __shared__ __align__(16) unsigned char smA[2][128*PITCH];
    __shared__ __align__(16) unsigned char smB[2][128*PITCH];
    const uint32 Ah = smem_u32(smA[0]), Al = smem_u32(smA[1]);
    const uint32 Bh = smem_u32(smB[0]), Bl = smem_u32(smB[1]);
    const int tid = threadIdx.x, lane = tid & 31, wid = tid >> 5;
    const int m0 = blockIdx.y * 128, n0 = blockIdx.x * 128;
    const int iw = (wid & 3) * 32, ow = (wid >> 2) * 64;

    float c[2][8][4];
    #pragma unroll
    for (int a = 0; a < 2; a++)
        #pragma unroll
        for (int b_ = 0; b_ < 8; b_++)
            #pragma unroll
            for (int d = 0; d < 4; d++) c[a][b_][d] = 0.f;

    const uint4* xh = (const uint4*)g_xh;  const uint4* xl = (const uint4*)g_xl;
    const uint4* wh = (const uint4*)g_WTh; const uint4* wl = (const uint4*)g_WTl;

    for (int kt = 0; kt < 256; kt += 32) {
        __syncthreads();
        #pragma unroll
        for (int p = 0; p < 2; p++) {
            int q = tid + p * 256;
            int row = q >> 2, seg = q & 3;
            uint32 off = (uint32)row * PITCH + seg * 16;
            size_t giA = (size_t)(m0 + row) * 32 + (kt >> 3) + seg;
            size_t giB = (size_t)(n0 + row) * 32 + (kt >> 3) + seg;
            sts128(Ah + off, xh[giA]);
            sts128(Al + off, xl[giA]);
            sts128(Bh + off, wh[giB]);
            sts128(Bl + off, wl[giB]);
        }
        __syncthreads();
        mma_chunk(c, Ah, Al, Bh, Bl, iw, ow, lane);
    }

    const int g = lane >> 2, cq = (lane & 3) * 2;
    #pragma unroll
    for (int mt = 0; mt < 2; mt++)
        #pragma unroll
        for (int nt = 0; nt < 8; nt++) {
            int m = m0 + iw + mt*16 + g;
            int o = n0 + ow + nt*8 + cq;
            *(float2*)&g_h[(size_t)m * FF + o]       = make_float2(c[mt][nt][0], c[mt][nt][1]);
            *(float2*)&g_h[(size_t)(m+8) * FF + o]   = make_float2(c[mt][nt][2], c[mt][nt][3]);
        }
}

// ============================================================
// s_kernel: s1/s2 row dots + exp tables
// ============================================================
__global__ void s_kernel(const float* __restrict__ a)
{
    int warp = threadIdx.x >> 5, lane = threadIdx.x & 31;
    int row = blockIdx.x * 8 + warp;
    const float* hr = &g_h[(size_t)row * 256];
    float s1 = 0.f, s2 = 0.f;
    #pragma unroll
    for (int q = 0; q < 8; q++) {
        int e = lane + 32 * q;
        float v = hr[e];
        s1 += v * __ldg(&a[e]);
        s2 += v * __ldg(&a[256 + e]);
    }
    #pragma unroll
    for (int o = 16; o > 0; o >>= 1) {
        s1 += __shfl_xor_sync(0xffffffffu, s1, o);
        s2 += __shfl_xor_sync(0xffffffffu, s2, o);
    }
    if (lane == 0) {
        g_s1[row] = s1; g_s2[row] = s2;
        g_E1[row]  = __expf(s1);        g_E2[row]  = __expf(s2);
        g_E1p[row] = __expf(0.2f * s1); g_E2p[row] = __expf(0.2f * s2);
    }
}

// ============================================================
// hsplit: transpose + bf16 hi/lo split of h -> g_hTh/g_hTl [b][o][j]
// ============================================================
__global__ void hsplit_kernel()
{
    __shared__ float t[64][33];
    const int b = blockIdx.z, j0 = blockIdx.x * 64, o0 = blockIdx.y * 32;
    const int tid = threadIdx.x;
    const int o = tid & 31, jr = tid >> 5;
    #pragma unroll
    for (int r = 0; r < 8; r++)
        t[jr + r*8][o] = g_h[((size_t)(b*NN + j0 + jr + r*8))*FF + o0 + o];
    __syncthreads();
    const int jl = (tid & 31) * 2, ob = tid >> 5;
    #pragma unroll
    for (int r = 0; r < 4; r++) {
        int oo = ob + r*8;
        uint32 hi, lo; split_pair(t[jl][oo], t[jl+1][oo], hi, lo);
        size_t pi = ((size_t)(b*FF + o0 + oo)) * (NN/2) + (j0 + jl)/2;
        g_hTh[pi] = hi;
        g_hTl[pi] = lo;
    }
}

// ============================================================
// zpass: Z[b,j] = sum_i adj * max(E1_i*E2_j, E1p_i*E2p_j)
// grid (2 jchunk, 8 iseg, 8 b), 256 thr, 4 j per thread (int4 adj)
// ============================================================
__global__ __launch_bounds__(256) void zpass_kernel(const int* __restrict__ adj)
{
    __shared__ float2 sE[256];
    const int b = blockIdx.z, iseg = blockIdx.y, tid = threadIdx.x;
    const int j = blockIdx.x * 1024 + tid * 4;
    const int ibase = iseg * 256;
    sE[tid] = make_float2(g_E1[b*NN + ibase + tid], g_E1p[b*NN + ibase + tid]);
    __syncthreads();
    float e0 = __ldg(&g_E2[b*NN+j]),   e1 = __ldg(&g_E2[b*NN+j+1]);
    float e2 = __ldg(&g_E2[b*NN+j+2]), e3 = __ldg(&g_E2[b*NN+j+3]);
    float p0 = __ldg(&g_E2p[b*NN+j]),   p1 = __ldg(&g_E2p[b*NN+j+1]);
    float p2 = __ldg(&g_E2p[b*NN+j+2]), p3 = __ldg(&g_E2p[b*NN+j+3]);
    const int4* ap = (const int4*)(adj + (size_t)(b*NN + ibase) * NN) + (j >> 2);
    float z0=0.f, z1=0.f, z2=0.f, z3=0.f;
    #pragma unroll 4
    for (int il = 0; il < 256; il++) {
        int4 av = __ldg(&ap[(size_t)il * (NN/4)]);
        float2 E = sE[il];
        float q0 = fmaxf(E.x*e0, E.y*p0);
        float q1 = fmaxf(E.x*e1, E.y*p1);
        float q2 = fmaxf(E.x*e2, E.y*p2);
        float q3 = fmaxf(E.x*e3, E.y*p3);
        if (av.x) z0 += q0;
        if (av.y) z1 += q1;
        if (av.z) z2 += q2;
        if (av.w) z3 += q3;
    }
    *(float4*)&g_Zp[(size_t)iseg * M_TOT + b*NN + j] = make_float4(z0, z1, z2, z3);
}

__global__ void zreduce_kernel()
{
    int idx = blockIdx.x * 256 + threadIdx.x;
    float z = 0.f;
    #pragma unroll
    for (int s = 0; s < 8; s++) z += g_Zp[(size_t)s * M_TOT + idx];
    float iz = 1.0f / z;
    g_u2[idx] = make_float2(g_E2[idx] * iz, g_E2p[idx] * iz);
}

// ============================================================
// attgemm v2: block = 128i x 256o, 512 thr (16 warps), double-buffered
// cp.async B tiles + register-prefetched adj/u2; on-the-fly A weights.
// grid (16 itile, 8 b).
// ============================================================
#define ST_A_HI 0
#define ST_A_LO 10240
#define ST_B_HI 20480
#define ST_B_LO 40960
#define STAGE   61440

__device__ __forceinline__ void genA(uint32 stg, const int2* radj, float4 ru2,
                                     int ibase, int jp, const float2* sE1)
{
    #pragma unroll
    for (int it = 0; it < 4; it++) {
        int i = ibase + it*32;
        float2 E = sE1[i];
        float q0 = fmaxf(E.x * ru2.x, E.y * ru2.y);
        float q1 = fmaxf(E.x * ru2.z, E.y * ru2.w);
        float w0 = radj[it].x ? q0 : 0.f;
        float w1 = radj[it].y ? q1 : 0.f;
        uint32 hi, lo; split_pair(w0, w1, hi, lo);
        uint32 off = (uint32)i * PITCH + jp * 4;
        sts32(stg + ST_A_HI + off, hi);
        sts32(stg + ST_A_LO + off, lo);
    }
}

__global__ __launch_bounds__(512,1) void attgemm_mma(
    const int* __restrict__ adj, float* __restrict__ out)
{
    extern __shared__ __align__(16) unsigned char dsm[];
    __shared__ float2 sE1[128];
    const uint32 sb = smem_u32(dsm);
    const int tid = threadIdx.x, lane = tid & 31, wid = tid >> 5;
    const int b = blockIdx.y, i0 = blockIdx.x * 128;
    const int iw = (wid & 3) * 32, ow = (wid >> 2) * 64;

    if (tid < 128)
        sE1[tid] = make_float2(g_E1[b*NN + i0 + tid], g_E1p[b*NN + i0 + tid]);

    float c[2][8][4];
    #pragma unroll
    for (int x = 0; x < 2; x++)
        #pragma unroll
        for (int y = 0; y < 8; y++)
            #pragma unroll
            for (int d = 0; d < 4; d++) c[x][y][d] = 0.f;

    // fixed per-thread coordinates
    const int jp    = tid & 15;
    const int ibase = tid >> 4;
    uint32 bdst[4]; const uint4* bsrc[4];
    #pragma unroll
    for (int p = 0; p < 4; p++) {
        int q = tid + p * 512;
        int half = q >> 10, r = q & 1023;
        int o = r >> 2, seg = r & 3;
        bdst[p] = (half ? ST_B_LO : ST_B_HI) + (uint32)o * PITCH + (uint32)seg * 16;
        bsrc[p] = (const uint4*)(half ? g_hTl : g_hTh)
                  + (size_t)(b*FF + o) * (NN/8) + seg;
    }
    const int2*   arow   = (const int2*)(adj + (size_t)(b*NN + i0) * NN);
    const float4* u2base = (const float4*)g_u2 + (size_t)(b*NN)/2;

    int2 radj[4]; float4 ru2;

    // ---- prologue: stage chunk 0 into buffer 0 ----
    {
        #pragma unroll
        for (int p = 0; p < 4; p++) cpa16(sb + bdst[p], bsrc[p]);
        CPA_COMMIT();
        #pragma unroll
        for (int it = 0; it < 4; it++)
            radj[it] = __ldg(&arow[(size_t)(ibase + it*32) * (NN/2) + jp]);
        ru2 = __ldg(&u2base[jp]);
        __syncthreads();                  // sE1 ready
        genA(sb, radj, ru2, ibase, jp, sE1);
        CPA_WAIT0();
        __syncthreads();
    }

    for (int cc = 0; cc < 64; cc++) {
        const int s = cc & 1;
        const uint32 stg  = sb + (uint32)s * STAGE;
        const uint32 stg1 = sb + (uint32)(s ^ 1) * STAGE;
        if (cc < 63) {
            const int j1 = (cc + 1) * 32;
            #pragma unroll
            for (int p = 0; p < 4; p++) cpa16(stg1 + bdst[p], bsrc[p] + (j1 >> 3));
            CPA_COMMIT();
            #pragma unroll
            for (int it = 0; it < 4; it++)
                radj[it] = __ldg(&arow[(size_t)(ibase + it*32) * (NN/2) + (j1 >> 1) + jp]);
            ru2 = __ldg(&u2base[(j1 >> 1) + jp]);
        }
        mma_chunk(c, stg + ST_A_HI, stg + ST_A_LO, stg + ST_B_HI, stg + ST_B_LO, iw, ow, lane);
        if (cc < 63) {
            genA(stg1, radj, ru2, ibase, jp, sE1);
            CPA_WAIT0();
        }
        __syncthreads();
    }

    // ---- epilogue: ELU + store ----
    const int g = lane >> 2, cq = (lane & 3) * 2;
    #pragma unroll
    for (int mt = 0; mt < 2; mt++)
        #pragma unroll
        for (int nt = 0; nt < 8; nt++) {
            int i = i0 + iw + mt*16 + g;
            int o = ow + nt*8 + cq;
            float f0 = c[mt][nt][0], f1 = c[mt][nt][1];
            float f2 = c[mt][nt][2], f3 = c[mt][nt][3];
            f0 = f0 > 0.f ? f0 : expm1f(f0);
            f1 = f1 > 0.f ? f1 : expm1f(f1);
            f2 = f2 > 0.f ? f2 : expm1f(f2);
            f3 = f3 > 0.f ? f3 : expm1f(f3);
            *(float2*)&out[((size_t)(b*NN + i))   * FF + o] = make_float2(f0, f1);
            *(float2*)&out[((size_t)(b*NN + i+8)) * FF + o] = make_float2(f2, f3);
        }
}

extern "C" void kernel_launch(void* const* d_in, const int* in_sizes, int n_in,
                              void* d_out, int out_size)
{
    const float* x   = (const float*)d_in[0];
    const int*   adj = (const int*)d_in[1];
    const float* W   = (const float*)d_in[2];
    const float* a   = (const float*)d_in[3];
    float* out = (float*)d_out;

    cudaFuncSetAttribute(attgemm_mma, cudaFuncAttributeMaxDynamicSharedMemorySize, 2*STAGE);

    xsplit_kernel<<<1024, 256>>>(x);
    wsplitT_kernel<<<128, 256>>>(W);
    gemm1_mma<<<dim3(2, 128), 256>>>();
    s_kernel<<<2048, 256>>>(a);
    hsplit_kernel<<<dim3(32, 8, 8), 256>>>();
    zpass_kernel<<<dim3(2, 8, 8), 256>>>(adj);
    zreduce_kernel<<<64, 256>>>();
    attgemm_mma<<<dim3(16, 8), 512, 2*STAGE>>>(adj, out);
}

// round 5
// speedup vs baseline: 2.7818x; 1.4042x over previous
#include <cuda_runtime.h>
#include <cuda_bf16.h>
#include <cuda_fp16.h>

typedef unsigned int uint32;

#define BB 8
#define NN 2048
#define FF 256
#define M_TOT (BB*NN)   // 16384
#define PITCH 80        // bytes per SMEM tile row (conflict-free ldmatrix)

// ---- scratch (device globals; no runtime allocations) ----
__device__ __align__(16) float g_h[M_TOT*FF];              // 16 MB fp32 h
__device__ float g_s1[M_TOT], g_s2[M_TOT];
__device__ float g_E1[M_TOT], g_E1p[M_TOT], g_E2[M_TOT], g_E2p[M_TOT];
__device__ __align__(16) float g_Zp[8*M_TOT];
__device__ __align__(16) float2 g_u2[M_TOT];               // (E2*invZ, E2p*invZ)
__device__ __align__(16) unsigned int g_hT16[M_TOT*FF/2];  // h^T fp16, [b][o][j-pairs]
__device__ __align__(16) unsigned int g_xh[M_TOT*FF/2];    // x bf16 hi, [m][k-pairs]
__device__ __align__(16) unsigned int g_xl[M_TOT*FF/2];
__device__ __align__(16) unsigned int g_WTh[FF*FF/2];      // W^T bf16 hi, [n][k-pairs]
__device__ __align__(16) unsigned int g_WTl[FF*FF/2];

// ================= helpers =================
__device__ __forceinline__ uint32 smem_u32(const void* p){
    uint32 a; asm("{ .reg .u64 t; cvta.to.shared.u64 t, %1; cvt.u32.u64 %0, t; }" : "=r"(a) : "l"(p));
    return a;
}
__device__ __forceinline__ uint32 pack_bf2(float a, float b){
    uint32 r; asm("cvt.rn.bf16x2.f32 %0, %1, %2;" : "=r"(r) : "f"(b), "f"(a)); return r;
}
__device__ __forceinline__ uint32 pack_f16x2(float a, float b){
    uint32 r; asm("cvt.rn.f16x2.f32 %0, %1, %2;" : "=r"(r) : "f"(b), "f"(a)); return r;
}
__device__ __forceinline__ void sts32(uint32 addr, uint32 v){
    asm volatile("st.shared.b32 [%0], %1;" :: "r"(addr), "r"(v) : "memory");
}
__device__ __forceinline__ void sts128(uint32 addr, uint4 v){
    asm volatile("st.shared.v4.b32 [%0], {%1,%2,%3,%4};"
        :: "r"(addr), "r"(v.x), "r"(v.y), "r"(v.z), "r"(v.w) : "memory");
}
__device__ __forceinline__ void ldm4(uint32* r, uint32 addr){
    asm volatile("ldmatrix.sync.aligned.m8n8.x4.shared.b16 {%0,%1,%2,%3}, [%4];"
        : "=r"(r[0]), "=r"(r[1]), "=r"(r[2]), "=r"(r[3]) : "r"(addr));
}
__device__ __forceinline__ void mma_bf16(float* c, const uint32* a, uint32 b0, uint32 b1){
    asm volatile("mma.sync.aligned.m16n8k16.row.col.f32.bf16.bf16.f32 "
        "{%0,%1,%2,%3}, {%4,%5,%6,%7}, {%8,%9}, {%0,%1,%2,%3};"
        : "+f"(c[0]), "+f"(c[1]), "+f"(c[2]), "+f"(c[3])
        : "r"(a[0]), "r"(a[1]), "r"(a[2]), "r"(a[3]), "r"(b0), "r"(b1));
}
__device__ __forceinline__ void mma_f16(float* c, const uint32* a, uint32 b0, uint32 b1){
    asm volatile("mma.sync.aligned.m16n8k16.row.col.f32.f16.f16.f32 "
        "{%0,%1,%2,%3}, {%4,%5,%6,%7}, {%8,%9}, {%0,%1,%2,%3};"
        : "+f"(c[0]), "+f"(c[1]), "+f"(c[2]), "+f"(c[3])
        : "r"(a[0]), "r"(a[1]), "r"(a[2]), "r"(a[3]), "r"(b0), "r"(b1));
}
__device__ __forceinline__ void cpa16(uint32 dst, const void* src){
    asm volatile("cp.async.cg.shared.global [%0], [%1], 16;" :: "r"(dst), "l"(src) : "memory");
}
#define CPA_COMMIT() asm volatile("cp.async.commit_group;" ::: "memory")
#define CPA_WAIT0()  asm volatile("cp.async.wait_group 0;" ::: "memory")

__device__ __forceinline__ void split_pair(float v0, float v1, uint32& hi, uint32& lo){
    hi = pack_bf2(v0, v1);
    float l0 = v0 - __uint_as_float(hi << 16);
    float l1 = v1 - __uint_as_float(hi & 0xFFFF0000u);
    lo = pack_bf2(l0, l1);
}

// ---- bf16 3-pass MMA core (gemm1 only) ----
__device__ __forceinline__ void mma_chunk(float c[2][8][4],
    uint32 Ah, uint32 Al, uint32 Bh, uint32 Bl, int iw, int ow, int lane)
{
    const uint32 base_off = (uint32)(lane & 15) * PITCH + (uint32)(lane >> 4) * 16;
    #pragma unroll
    for (int ks = 0; ks < 2; ks++) {
        const uint32 off = base_off + ks * 32;
        uint32 A0[4], A1[4], A0l[4], A1l[4], B[4][4];
        ldm4(A0, Ah + (uint32)iw * PITCH + off);
        ldm4(A1, Ah + (uint32)(iw + 16) * PITCH + off);
        #pragma unroll
        for (int t = 0; t < 4; t++) ldm4(B[t], Bh + (uint32)(ow + t*16) * PITCH + off);
        #pragma unroll
        for (int t = 0; t < 4; t++) {
            mma_bf16(c[0][t*2+0], A0, B[t][0], B[t][2]);
            mma_bf16(c[1][t*2+0], A1, B[t][0], B[t][2]);
            mma_bf16(c[0][t*2+1], A0, B[t][1], B[t][3]);
            mma_bf16(c[1][t*2+1], A1, B[t][1], B[t][3]);
        }
        ldm4(A0l, Al + (uint32)iw * PITCH + off);
        ldm4(A1l, Al + (uint32)(iw + 16) * PITCH + off);
        #pragma unroll
        for (int t = 0; t < 4; t++) {
            mma_bf16(c[0][t*2+0], A0l, B[t][0], B[t][2]);
            mma_bf16(c[1][t*2+0], A1l, B[t][0], B[t][2]);
            mma_bf16(c[0][t*2+1], A0l, B[t][1], B[t][3]);
            mma_bf16(c[1][t*2+1], A1l, B[t][1], B[t][3]);
        }
        #pragma unroll
        for (int t = 0; t < 4; t++) ldm4(B[t], Bl + (uint32)(ow + t*16) * PITCH + off);
        #pragma unroll
        for (int t = 0; t < 4; t++) {
            mma_bf16(c[0][t*2+0], A0, B[t][0], B[t][2]);
            mma_bf16(c[1][t*2+0], A1, B[t][0], B[t][2]);
            mma_bf16(c[0][t*2+1], A0, B[t][1], B[t][3]);
            mma_bf16(c[1][t*2+1], A1, B[t][1], B[t][3]);
        }
    }
}

// ---- fp16 single-pass MMA core (attgemm) ----
__device__ __forceinline__ void mma_chunk_f16(float c[2][8][4],
    uint32 A, uint32 B, int iw, int ow, int lane)
{
    const uint32 base_off = (uint32)(lane & 15) * PITCH + (uint32)(lane >> 4) * 16;
    #pragma unroll
    for (int ks = 0; ks < 2; ks++) {
        const uint32 off = base_off + ks * 32;
        uint32 A0[4], A1[4], Bt[4][4];
        ldm4(A0, A + (uint32)iw * PITCH + off);
        ldm4(A1, A + (uint32)(iw + 16) * PITCH + off);
        #pragma unroll
        for (int t = 0; t < 4; t++) ldm4(Bt[t], B + (uint32)(ow + t*16) * PITCH + off);
        #pragma unroll
        for (int t = 0; t < 4; t++) {
            mma_f16(c[0][t*2+0], A0, Bt[t][0], Bt[t][2]);
            mma_f16(c[1][t*2+0], A1, Bt[t][0], Bt[t][2]);
            mma_f16(c[0][t*2+1], A0, Bt[t][1], Bt[t][3]);
            mma_f16(c[1][t*2+1], A1, Bt[t][1], Bt[t][3]);
        }
    }
}

// ============================================================
// xsplit: x fp32 -> bf16 hi/lo pairs [m][k/2]
// ============================================================
__global__ void xsplit_kernel(const float* __restrict__ x)
{
    int idx = blockIdx.x * 256 + threadIdx.x;
    #pragma unroll
    for (int r = 0; r < 8; r++) {
        int p = idx + r * 262144;
        float2 v = ((const float2*)x)[p];
        uint32 hi, lo; split_pair(v.x, v.y, hi, lo);
        g_xh[p] = hi; g_xl[p] = lo;
    }
}

// ============================================================
// wsplitT: W [k][n] fp32 -> W^T bf16 hi/lo [n][k/2]
// ============================================================
__global__ void wsplitT_kernel(const float* __restrict__ W)
{
    int idx = blockIdx.x * 256 + threadIdx.x;
    int n = idx >> 7, kp = idx & 127;
    float v0 = W[(size_t)(2*kp)   * FF + n];
    float v1 = W[(size_t)(2*kp+1) * FF + n];
    uint32 hi, lo; split_pair(v0, v1, hi, lo);
    g_WTh[n*128 + kp] = hi; g_WTl[n*128 + kp] = lo;
}

// ============================================================
// gemm1: h = x @ W  via bf16 HMMA 3-pass (precision-critical: feeds exp)
// ============================================================
__global__ __launch_bounds__(256,2) void gemm1_mma(void)
{
    __shared__ __align__(16) unsigned char smA[2][128*PITCH];
    __shared__ __align__(16) unsigned char smB[2][128*PITCH];
    const uint32 Ah = smem_u32(smA[0]), Al = smem_u32(smA[1]);
    const uint32 Bh = smem_u32(smB[0]), Bl = smem_u32(smB[1]);
    const int tid = threadIdx.x, lane = tid & 31, wid = tid >> 5;
    const int m0 = blockIdx.y * 128, n0 = blockIdx.x * 128;
    const int iw = (wid & 3) * 32, ow = (wid >> 2) * 64;

    float c[2][8][4];
    #pragma unroll
    for (int a = 0; a < 2; a++)
        #pragma unroll
        for (int b_ = 0; b_ < 8; b_++)
            #pragma unroll
            for (int d = 0; d < 4; d++) c[a][b_][d] = 0.f;

    const uint4* xh = (const uint4*)g_xh;  const uint4* xl = (const uint4*)g_xl;
    const uint4* wh = (const uint4*)g_WTh; const uint4* wl = (const uint4*)g_WTl;

    for (int kt = 0; kt < 256; kt += 32) {
        __syncthreads();
        #pragma unroll
        for (int p = 0; p < 2; p++) {
            int q = tid + p * 256;
            int row = q >> 2, seg = q & 3;
            uint32 off = (uint32)row * PITCH + seg * 16;
            size_t giA = (size_t)(m0 + row) * 32 + (kt >> 3) + seg;
            size_t giB = (size_t)(n0 + row) * 32 + (kt >> 3) + seg;
            sts128(Ah + off, xh[giA]);
            sts128(Al + off, xl[giA]);
            sts128(Bh + off, wh[giB]);
            sts128(Bl + off, wl[giB]);
        }
        __syncthreads();
        mma_chunk(c, Ah, Al, Bh, Bl, iw, ow, lane);
    }

    const int g = lane >> 2, cq = (lane & 3) * 2;
    #pragma unroll
    for (int mt = 0; mt < 2; mt++)
        #pragma unroll
        for (int nt = 0; nt < 8; nt++) {
            int m = m0 + iw + mt*16 + g;
            int o = n0 + ow + nt*8 + cq;
            *(float2*)&g_h[(size_t)m * FF + o]       = make_float2(c[mt][nt][0], c[mt][nt][1]);
            *(float2*)&g_h[(size_t)(m+8) * FF + o]   = make_float2(c[mt][nt][2], c[mt][nt][3]);
        }
}

// ============================================================
// s_kernel: s1/s2 row dots + exp tables
// ============================================================
__global__ void s_kernel(const float* __restrict__ a)
{
    int warp = threadIdx.x >> 5, lane = threadIdx.x & 31;
    int row = blockIdx.x * 8 + warp;
    const float* hr = &g_h[(size_t)row * 256];
    float s1 = 0.f, s2 = 0.f;
    #pragma unroll
    for (int q = 0; q < 8; q++) {
        int e = lane + 32 * q;
        float v = hr[e];
        s1 += v * __ldg(&a[e]);
        s2 += v * __ldg(&a[256 + e]);
    }
    #pragma unroll
    for (int o = 16; o > 0; o >>= 1) {
        s1 += __shfl_xor_sync(0xffffffffu, s1, o);
        s2 += __shfl_xor_sync(0xffffffffu, s2, o);
    }
    if (lane == 0) {
        g_s1[row] = s1; g_s2[row] = s2;
        g_E1[row]  = __expf(s1);        g_E2[row]  = __expf(s2);
        g_E1p[row] = __expf(0.2f * s1); g_E2p[row] = __expf(0.2f * s2);
    }
}

// ============================================================
// hsplit: transpose h -> fp16 h^T [b][o][j]
// ============================================================
__global__ void hsplit_kernel()
{
    __shared__ float t[64][33];
    const int b = blockIdx.z, j0 = blockIdx.x * 64, o0 = blockIdx.y * 32;
    const int tid = threadIdx.x;
    const int o = tid & 31, jr = tid >> 5;
    #pragma unroll
    for (int r = 0; r < 8; r++)
        t[jr + r*8][o] = g_h[((size_t)(b*NN + j0 + jr + r*8))*FF + o0 + o];
    __syncthreads();
    const int jl = (tid & 31) * 2, ob = tid >> 5;
    #pragma unroll
    for (int r = 0; r < 4; r++) {
        int oo = ob + r*8;
        size_t pi = ((size_t)(b*FF + o0 + oo)) * (NN/2) + (j0 + jl)/2;
        g_hT16[pi] = pack_f16x2(t[jl][oo], t[jl+1][oo]);
    }
}

// ============================================================
// zpass: Z[b,j] = e_j * sum_i adj * max(E1_i, r_j*E1p_i),  r_j = ep_j/e_j
// grid (2 jchunk, 8 iseg, 8 b), 256 thr, 4 j per thread (int4 adj)
// ============================================================
__global__ __launch_bounds__(256) void zpass_kernel(const int* __restrict__ adj)
{
    __shared__ float2 sE[256];
    const int b = blockIdx.z, iseg = blockIdx.y, tid = threadIdx.x;
    const int j = blockIdx.x * 1024 + tid * 4;
    const int ibase = iseg * 256;
    sE[tid] = make_float2(g_E1[b*NN + ibase + tid], g_E1p[b*NN + ibase + tid]);
    __syncthreads();
    float e0 = __ldg(&g_E2[b*NN+j]),   e1 = __ldg(&g_E2[b*NN+j+1]);
    float e2 = __ldg(&g_E2[b*NN+j+2]), e3 = __ldg(&g_E2[b*NN+j+3]);
    float r0 = __ldg(&g_E2p[b*NN+j])   / e0, r1 = __ldg(&g_E2p[b*NN+j+1]) / e1;
    float r2 = __ldg(&g_E2p[b*NN+j+2]) / e2, r3 = __ldg(&g_E2p[b*NN+j+3]) / e3;
    const int4* ap = (const int4*)(adj + (size_t)(b*NN + ibase) * NN) + (j >> 2);
    float z0=0.f, z1=0.f, z2=0.f, z3=0.f;
    #pragma unroll 8
    for (int il = 0; il < 256; il++) {
        int4 av = __ldg(&ap[(size_t)il * (NN/4)]);
        float2 E = sE[il];
        float q0 = fmaxf(E.x, r0*E.y);
        float q1 = fmaxf(E.x, r1*E.y);
        float q2 = fmaxf(E.x, r2*E.y);
        float q3 = fmaxf(E.x, r3*E.y);
        if (av.x) z0 += q0;
        if (av.y) z1 += q1;
        if (av.z) z2 += q2;
        if (av.w) z3 += q3;
    }
    *(float4*)&g_Zp[(size_t)iseg * M_TOT + b*NN + j] = make_float4(z0*e0, z1*e1, z2*e2, z3*e3);
}

__global__ void zreduce_kernel()
{
    int idx = blockIdx.x * 256 + threadIdx.x;
    float z = 0.f;
    #pragma unroll
    for (int s = 0; s < 8; s++) z += g_Zp[(size_t)s * M_TOT + idx];
    float iz = 1.0f / z;
    g_u2[idx] = make_float2(g_E2[idx] * iz, g_E2p[idx] * iz);
}

// ============================================================
// attgemm v3: fp16 single-pass. block = 128i x 256o, 512 thr,
// double-buffered cp.async B + register-prefetched adj/u2.
// grid (16 itile, 8 b).
// ============================================================
#define ST_A   0
#define ST_B   10240
#define STAGE  30720

__device__ __forceinline__ void genA(uint32 stg, const int2* radj, float4 ru2,
                                     int ibase, int jp, const float2* E)
{
    #pragma unroll
    for (int it = 0; it < 4; it++) {
        float q0 = fmaxf(E[it].x * ru2.x, E[it].y * ru2.y);
        float q1 = fmaxf(E[it].x * ru2.z, E[it].y * ru2.w);
        float w0 = radj[it].x ? q0 : 0.f;
        float w1 = radj[it].y ? q1 : 0.f;
        sts32(stg + ST_A + (uint32)(ibase + it*32) * PITCH + jp * 4, pack_f16x2(w0, w1));
    }
}

__global__ __launch_bounds__(512,1) void attgemm_mma(
    const int* __restrict__ adj, float* __restrict__ out)
{
    extern __shared__ __align__(16) unsigned char dsm[];
    __shared__ float2 sE1[128];
    const uint32 sb = smem_u32(dsm);
    const int tid = threadIdx.x, lane = tid & 31, wid = tid >> 5;
    const int b = blockIdx.y, i0 = blockIdx.x * 128;
    const int iw = (wid & 3) * 32, ow = (wid >> 2) * 64;

    if (tid < 128)
        sE1[tid] = make_float2(g_E1[b*NN + i0 + tid], g_E1p[b*NN + i0 + tid]);

    float c[2][8][4];
    #pragma unroll
    for (int x = 0; x < 2; x++)
        #pragma unroll
        for (int y = 0; y < 8; y++)
            #pragma unroll
            for (int d = 0; d < 4; d++) c[x][y][d] = 0.f;

    const int jp    = tid & 15;
    const int ibase = tid >> 4;
    uint32 bdst[2]; const uint4* bsrc[2];
    #pragma unroll
    for (int p = 0; p < 2; p++) {
        int q = tid + p * 512;            // 0..1023
        int o = q >> 2, seg = q & 3;
        bdst[p] = ST_B + (uint32)o * PITCH + (uint32)seg * 16;
        bsrc[p] = (const uint4*)g_hT16 + (size_t)(b*FF + o) * (NN/8) + seg;
    }
    const int2*   arow   = (const int2*)(adj + (size_t)(b*NN + i0) * NN);
    const float4* u2base = (const float4*)g_u2 + (size_t)(b*NN)/2;

    int2 radj[4]; float4 ru2; float2 E[4];

    // ---- prologue ----
    {
        #pragma unroll
        for (int p = 0; p < 2; p++) cpa16(sb + bdst[p], bsrc[p]);
        CPA_COMMIT();
        #pragma unroll
        for (int it = 0; it < 4; it++)
            radj[it] = __ldg(&arow[(size_t)(ibase + it*32) * (NN/2) + jp]);
        ru2 = __ldg(&u2base[jp]);
        __syncthreads();                  // sE1 ready
        #pragma unroll
        for (int it = 0; it < 4; it++) E[it] = sE1[ibase + it*32];
        genA(sb, radj, ru2, ibase, jp, E);
        CPA_WAIT0();
        __syncthreads();
    }

    for (int cc = 0; cc < 64; cc++) {
        const int s = cc & 1;
        const uint32 stg  = sb + (uint32)s * STAGE;
        const uint32 stg1 = sb + (uint32)(s ^ 1) * STAGE;
        if (cc < 63) {
            const int j1 = (cc + 1) * 32;
            #pragma unroll
            for (int p = 0; p < 2; p++) cpa16(stg1 + bdst[p], bsrc[p] + (j1 >> 3));
            CPA_COMMIT();
            #pragma unroll
            for (int it = 0; it < 4; it++)
                radj[it] = __ldg(&arow[(size_t)(ibase + it*32) * (NN/2) + (j1 >> 1) + jp]);
            ru2 = __ldg(&u2base[(j1 >> 1) + jp]);
        }
        mma_chunk_f16(c, stg + ST_A, stg + ST_B, iw, ow, lane);
        if (cc < 63) {
            genA(stg1, radj, ru2, ibase, jp, E);
            CPA_WAIT0();
        }
        __syncthreads();
    }

    // ---- epilogue: ELU + store ----
    const int g = lane >> 2, cq = (lane & 3) * 2;
    #pragma unroll
    for (int mt = 0; mt < 2; mt++)
        #pragma unroll
        for (int nt = 0; nt < 8; nt++) {
            int i = i0 + iw + mt*16 + g;
            int o = ow + nt*8 + cq;
            float f0 = c[mt][nt][0], f1 = c[mt][nt][1];
            float f2 = c[mt][nt][2], f3 = c[mt][nt][3];
            f0 = f0 > 0.f ? f0 : expm1f(f0);
            f1 = f1 > 0.f ? f1 : expm1f(f1);
            f2 = f2 > 0.f ? f2 : expm1f(f2);
            f3 = f3 > 0.f ? f3 : expm1f(f3);
            *(float2*)&out[((size_t)(b*NN + i))   * FF + o] = make_float2(f0, f1);
            *(float2*)&out[((size_t)(b*NN + i+8)) * FF + o] = make_float2(f2, f3);
        }
}

extern "C" void kernel_launch(void* const* d_in, const int* in_sizes, int n_in,
                              void* d_out, int out_size)
{
    const float* x   = (const float*)d_in[0];
    const int*   adj = (const int*)d_in[1];
    const float* W   = (const float*)d_in[2];
    const float* a   = (const float*)d_in[3];
    float* out = (float*)d_out;

    cudaFuncSetAttribute(attgemm_mma, cudaFuncAttributeMaxDynamicSharedMemorySize, 2*STAGE);

    xsplit_kernel<<<1024, 256>>>(x);
    wsplitT_kernel<<<128, 256>>>(W);
    gemm1_mma<<<dim3(2, 128), 256>>>();
    s_kernel<<<2048, 256>>>(a);
    hsplit_kernel<<<dim3(32, 8, 8), 256>>>();
    zpass_kernel<<<dim3(2, 8, 8), 256>>>(adj);
    zreduce_kernel<<<64, 256>>>();
    attgemm_mma<<<dim3(16, 8), 512, 2*STAGE>>>(adj, out);
}

// round 6
// speedup vs baseline: 3.4277x; 1.2322x over previous
#include <cuda_runtime.h>
#include <cuda_bf16.h>
#include <cuda_fp16.h>

typedef unsigned int uint32;

#define BB 8
#define NN 2048
#define FF 256
#define M_TOT (BB*NN)   // 16384
#define PITCH 80        // bytes per SMEM tile row (conflict-free ldmatrix)

// ---- scratch (device globals; no runtime allocations) ----
__device__ __align__(16) float g_h[M_TOT*FF];              // 16 MB fp32 h
__device__ float g_s1[M_TOT], g_s2[M_TOT];
__device__ float g_E1[M_TOT], g_E1p[M_TOT], g_E2[M_TOT], g_E2p[M_TOT];
__device__ __align__(16) float g_Zp[32*M_TOT];             // 2 MB partials
__device__ __align__(16) float2 g_u2[M_TOT];               // (E2*invZ, E2p*invZ)
__device__ __align__(16) unsigned int g_hT16[M_TOT*FF/2];  // h^T fp16, [b][o][j-pairs]
__device__ __align__(16) unsigned int g_xh[M_TOT*FF/2];    // x bf16 hi, [m][k-pairs]
__device__ __align__(16) unsigned int g_xl[M_TOT*FF/2];
__device__ __align__(16) unsigned int g_WTh[FF*FF/2];      // W^T bf16 hi, [n][k-pairs]
__device__ __align__(16) unsigned int g_WTl[FF*FF/2];

// ================= helpers =================
__device__ __forceinline__ uint32 smem_u32(const void* p){
    uint32 a; asm("{ .reg .u64 t; cvta.to.shared.u64 t, %1; cvt.u32.u64 %0, t; }" : "=r"(a) : "l"(p));
    return a;
}
__device__ __forceinline__ uint32 pack_bf2(float a, float b){
    uint32 r; asm("cvt.rn.bf16x2.f32 %0, %1, %2;" : "=r"(r) : "f"(b), "f"(a)); return r;
}
__device__ __forceinline__ uint32 pack_f16x2(float a, float b){
    uint32 r; asm("cvt.rn.f16x2.f32 %0, %1, %2;" : "=r"(r) : "f"(b), "f"(a)); return r;
}
__device__ __forceinline__ void sts32(uint32 addr, uint32 v){
    asm volatile("st.shared.b32 [%0], %1;" :: "r"(addr), "r"(v) : "memory");
}
__device__ __forceinline__ void sts128(uint32 addr, uint4 v){
    asm volatile("st.shared.v4.b32 [%0], {%1,%2,%3,%4};"
        :: "r"(addr), "r"(v.x), "r"(v.y), "r"(v.z), "r"(v.w) : "memory");
}
__device__ __forceinline__ void ldm4(uint32* r, uint32 addr){
    asm volatile("ldmatrix.sync.aligned.m8n8.x4.shared.b16 {%0,%1,%2,%3}, [%4];"
        : "=r"(r[0]), "=r"(r[1]), "=r"(r[2]), "=r"(r[3]) : "r"(addr));
}
__device__ __forceinline__ void mma_bf16(float* c, const uint32* a, uint32 b0, uint32 b1){
    asm volatile("mma.sync.aligned.m16n8k16.row.col.f32.bf16.bf16.f32 "
        "{%0,%1,%2,%3}, {%4,%5,%6,%7}, {%8,%9}, {%0,%1,%2,%3};"
        : "+f"(c[0]), "+f"(c[1]), "+f"(c[2]), "+f"(c[3])
        : "r"(a[0]), "r"(a[1]), "r"(a[2]), "r"(a[3]), "r"(b0), "r"(b1));
}
__device__ __forceinline__ void mma_f16(float* c, const uint32* a, uint32 b0, uint32 b1){
    asm volatile("mma.sync.aligned.m16n8k16.row.col.f32.f16.f16.f32 "
        "{%0,%1,%2,%3}, {%4,%5,%6,%7}, {%8,%9}, {%0,%1,%2,%3};"
        : "+f"(c[0]), "+f"(c[1]), "+f"(c[2]), "+f"(c[3])
        : "r"(a[0]), "r"(a[1]), "r"(a[2]), "r"(a[3]), "r"(b0), "r"(b1));
}
__device__ __forceinline__ void cpa16(uint32 dst, const void* src){
    asm volatile("cp.async.cg.shared.global [%0], [%1], 16;" :: "r"(dst), "l"(src) : "memory");
}
#define CPA_COMMIT() asm volatile("cp.async.commit_group;" ::: "memory")
#define CPA_WAIT0()  asm volatile("cp.async.wait_group 0;" ::: "memory")

__device__ __forceinline__ void split_pair(float v0, float v1, uint32& hi, uint32& lo){
    hi = pack_bf2(v0, v1);
    float l0 = v0 - __uint_as_float(hi << 16);
    float l1 = v1 - __uint_as_float(hi & 0xFFFF0000u);
    lo = pack_bf2(l0, l1);
}

// ---- bf16 3-pass MMA core (gemm1 only) ----
__device__ __forceinline__ void mma_chunk(float c[2][8][4],
    uint32 Ah, uint32 Al, uint32 Bh, uint32 Bl, int iw, int ow, int lane)
{
    const uint32 base_off = (uint32)(lane & 15) * PITCH + (uint32)(lane >> 4) * 16;
    #pragma unroll
    for (int ks = 0; ks < 2; ks++) {
        const uint32 off = base_off + ks * 32;
        uint32 A0[4], A1[4], A0l[4], A1l[4], B[4][4];
        ldm4(A0, Ah + (uint32)iw * PITCH + off);
        ldm4(A1, Ah + (uint32)(iw + 16) * PITCH + off);
        #pragma unroll
        for (int t = 0; t < 4; t++) ldm4(B[t], Bh + (uint32)(ow + t*16) * PITCH + off);
        #pragma unroll
        for (int t = 0; t < 4; t++) {
            mma_bf16(c[0][t*2+0], A0, B[t][0], B[t][2]);
            mma_bf16(c[1][t*2+0], A1, B[t][0], B[t][2]);
            mma_bf16(c[0][t*2+1], A0, B[t][1], B[t][3]);
            mma_bf16(c[1][t*2+1], A1, B[t][1], B[t][3]);
        }
        ldm4(A0l, Al + (uint32)iw * PITCH + off);
        ldm4(A1l, Al + (uint32)(iw + 16) * PITCH + off);
        #pragma unroll
        for (int t = 0; t < 4; t++) {
            mma_bf16(c[0][t*2+0], A0l, B[t][0], B[t][2]);
            mma_bf16(c[1][t*2+0], A1l, B[t][0], B[t][2]);
            mma_bf16(c[0][t*2+1], A0l, B[t][1], B[t][3]);
            mma_bf16(c[1][t*2+1], A1l, B[t][1], B[t][3]);
        }
        #pragma unroll
        for (int t = 0; t < 4; t++) ldm4(B[t], Bl + (uint32)(ow + t*16) * PITCH + off);
        #pragma unroll
        for (int t = 0; t < 4; t++) {
            mma_bf16(c[0][t*2+0], A0, B[t][0], B[t][2]);
            mma_bf16(c[1][t*2+0], A1, B[t][0], B[t][2]);
            mma_bf16(c[0][t*2+1], A0, B[t][1], B[t][3]);
            mma_bf16(c[1][t*2+1], A1, B[t][1], B[t][3]);
        }
    }
}

// ---- fp16 single-pass MMA core (attgemm) ----
__device__ __forceinline__ void mma_chunk_f16(float c[2][8][4],
    uint32 A, uint32 B, int iw, int ow, int lane)
{
    const uint32 base_off = (uint32)(lane & 15) * PITCH + (uint32)(lane >> 4) * 16;
    #pragma unroll
    for (int ks = 0; ks < 2; ks++) {
        const uint32 off = base_off + ks * 32;
        uint32 A0[4], A1[4], Bt[4][4];
        ldm4(A0, A + (uint32)iw * PITCH + off);
        ldm4(A1, A + (uint32)(iw + 16) * PITCH + off);
        #pragma unroll
        for (int t = 0; t < 4; t++) ldm4(Bt[t], B + (uint32)(ow + t*16) * PITCH + off);
        #pragma unroll
        for (int t = 0; t < 4; t++) {
            mma_f16(c[0][t*2+0], A0, Bt[t][0], Bt[t][2]);
            mma_f16(c[1][t*2+0], A1, Bt[t][0], Bt[t][2]);
            mma_f16(c[0][t*2+1], A0, Bt[t][1], Bt[t][3]);
            mma_f16(c[1][t*2+1], A1, Bt[t][1], Bt[t][3]);
        }
    }
}

// ============================================================
// xsplit: x fp32 -> bf16 hi/lo pairs [m][k/2]
// ============================================================
__global__ void xsplit_kernel(const float* __restrict__ x)
{
    int idx = blockIdx.x * 256 + threadIdx.x;
    #pragma unroll
    for (int r = 0; r < 8; r++) {
        int p = idx + r * 262144;
        float2 v = ((const float2*)x)[p];
        uint32 hi, lo; split_pair(v.x, v.y, hi, lo);
        g_xh[p] = hi; g_xl[p] = lo;
    }
}

// ============================================================
// wsplitT: W [k][n] fp32 -> W^T bf16 hi/lo [n][k/2]
// ============================================================
__global__ void wsplitT_kernel(const float* __restrict__ W)
{
    int idx = blockIdx.x * 256 + threadIdx.x;
    int n = idx >> 7, kp = idx & 127;
    float v0 = W[(size_t)(2*kp)   * FF + n];
    float v1 = W[(size_t)(2*kp+1) * FF + n];
    uint32 hi, lo; split_pair(v0, v1, hi, lo);
    g_WTh[n*128 + kp] = hi; g_WTl[n*128 + kp] = lo;
}

// ============================================================
// gemm1: h = x @ W  via bf16 HMMA 3-pass (precision-critical: feeds exp)
// ============================================================
__global__ __launch_bounds__(256,2) void gemm1_mma(void)
{
    __shared__ __align__(16) unsigned char smA[2][128*PITCH];
    __shared__ __align__(16) unsigned char smB[2][128*PITCH];
    const uint32 Ah = smem_u32(smA[0]), Al = smem_u32(smA[1]);
    const uint32 Bh = smem_u32(smB[0]), Bl = smem_u32(smB[1]);
    const int tid = threadIdx.x, lane = tid & 31, wid = tid >> 5;
    const int m0 = blockIdx.y * 128, n0 = blockIdx.x * 128;
    const int iw = (wid & 3) * 32, ow = (wid >> 2) * 64;

    float c[2][8][4];
    #pragma unroll
    for (int a = 0; a < 2; a++)
        #pragma unroll
        for (int b_ = 0; b_ < 8; b_++)
            #pragma unroll
            for (int d = 0; d < 4; d++) c[a][b_][d] = 0.f;

    const uint4* xh = (const uint4*)g_xh;  const uint4* xl = (const uint4*)g_xl;
    const uint4* wh = (const uint4*)g_WTh; const uint4* wl = (const uint4*)g_WTl;

    for (int kt = 0; kt < 256; kt += 32) {
        __syncthreads();
        #pragma unroll
        for (int p = 0; p < 2; p++) {
            int q = tid + p * 256;
            int row = q >> 2, seg = q & 3;
            uint32 off = (uint32)row * PITCH + seg * 16;
            size_t giA = (size_t)(m0 + row) * 32 + (kt >> 3) + seg;
            size_t giB = (size_t)(n0 + row) * 32 + (kt >> 3) + seg;
            sts128(Ah + off, xh[giA]);
            sts128(Al + off, xl[giA]);
            sts128(Bh + off, wh[giB]);
            sts128(Bl + off, wl[giB]);
        }
        __syncthreads();
        mma_chunk(c, Ah, Al, Bh, Bl, iw, ow, lane);
    }

    const int g = lane >> 2, cq = (lane & 3) * 2;
    #pragma unroll
    for (int mt = 0; mt < 2; mt++)
        #pragma unroll
        for (int nt = 0; nt < 8; nt++) {
            int m = m0 + iw + mt*16 + g;
            int o = n0 + ow + nt*8 + cq;
            *(float2*)&g_h[(size_t)m * FF + o]       = make_float2(c[mt][nt][0], c[mt][nt][1]);
            *(float2*)&g_h[(size_t)(m+8) * FF + o]   = make_float2(c[mt][nt][2], c[mt][nt][3]);
        }
}

// ============================================================
// s_kernel: s1/s2 row dots + exp tables
// ============================================================
__global__ void s_kernel(const float* __restrict__ a)
{
    int warp = threadIdx.x >> 5, lane = threadIdx.x & 31;
    int row = blockIdx.x * 8 + warp;
    const float* hr = &g_h[(size_t)row * 256];
    float s1 = 0.f, s2 = 0.f;
    #pragma unroll
    for (int q = 0; q < 8; q++) {
        int e = lane + 32 * q;
        float v = hr[e];
        s1 += v * __ldg(&a[e]);
        s2 += v * __ldg(&a[256 + e]);
    }
    #pragma unroll
    for (int o = 16; o > 0; o >>= 1) {
        s1 += __shfl_xor_sync(0xffffffffu, s1, o);
        s2 += __shfl_xor_sync(0xffffffffu, s2, o);
    }
    if (lane == 0) {
        g_s1[row] = s1; g_s2[row] = s2;
        g_E1[row]  = __expf(s1);        g_E2[row]  = __expf(s2);
        g_E1p[row] = __expf(0.2f * s1); g_E2p[row] = __expf(0.2f * s2);
    }
}

// ============================================================
// hsplit: transpose h -> fp16 h^T [b][o][j]
// ============================================================
__global__ void hsplit_kernel()
{
    __shared__ float t[64][33];
    const int b = blockIdx.z, j0 = blockIdx.x * 64, o0 = blockIdx.y * 32;
    const int tid = threadIdx.x;
    const int o = tid & 31, jr = tid >> 5;
    #pragma unroll
    for (int r = 0; r < 8; r++)
        t[jr + r*8][o] = g_h[((size_t)(b*NN + j0 + jr + r*8))*FF + o0 + o];
    __syncthreads();
    const int jl = (tid & 31) * 2, ob = tid >> 5;
    #pragma unroll
    for (int r = 0; r < 4; r++) {
        int oo = ob + r*8;
        size_t pi = ((size_t)(b*FF + o0 + oo)) * (NN/2) + (j0 + jl)/2;
        g_hT16[pi] = pack_f16x2(t[jl][oo], t[jl+1][oo]);
    }
}

// ============================================================
// zpass: Z[b,j] = e_j * sum_i adj * max(E1_i, r_j*E1p_i),  r_j = ep_j/e_j
// grid (2 jchunk, 32 iseg, 8 b) = 512 blocks, 256 thr, 4 j/thread (int4 adj)
// ============================================================
__global__ __launch_bounds__(256) void zpass_kernel(const int* __restrict__ adj)
{
    __shared__ float2 sE[64];
    const int b = blockIdx.z, iseg = blockIdx.y, tid = threadIdx.x;
    const int j = blockIdx.x * 1024 + tid * 4;
    const int ibase = iseg * 64;
    if (tid < 64)
        sE[tid] = make_float2(g_E1[b*NN + ibase + tid], g_E1p[b*NN + ibase + tid]);
    __syncthreads();
    float e0 = __ldg(&g_E2[b*NN+j]),   e1 = __ldg(&g_E2[b*NN+j+1]);
    float e2 = __ldg(&g_E2[b*NN+j+2]), e3 = __ldg(&g_E2[b*NN+j+3]);
    float r0 = __ldg(&g_E2p[b*NN+j])   / e0, r1 = __ldg(&g_E2p[b*NN+j+1]) / e1;
    float r2 = __ldg(&g_E2p[b*NN+j+2]) / e2, r3 = __ldg(&g_E2p[b*NN+j+3]) / e3;
    const int4* ap = (const int4*)(adj + (size_t)(b*NN + ibase) * NN) + (j >> 2);
    float z0=0.f, z1=0.f, z2=0.f, z3=0.f;
    #pragma unroll 8
    for (int il = 0; il < 64; il++) {
        int4 av = __ldg(&ap[(size_t)il * (NN/4)]);
        float2 E = sE[il];
        float q0 = fmaxf(E.x, r0*E.y);
        float q1 = fmaxf(E.x, r1*E.y);
        float q2 = fmaxf(E.x, r2*E.y);
        float q3 = fmaxf(E.x, r3*E.y);
        if (av.x) z0 += q0;
        if (av.y) z1 += q1;
        if (av.z) z2 += q2;
        if (av.w) z3 += q3;
    }
    *(float4*)&g_Zp[(size_t)iseg * M_TOT + b*NN + j] = make_float4(z0*e0, z1*e1, z2*e2, z3*e3);
}

__global__ void zreduce_kernel()
{
    int idx = blockIdx.x * 256 + threadIdx.x;
    float z = 0.f;
    #pragma unroll
    for (int s = 0; s < 32; s++) z += g_Zp[(size_t)s * M_TOT + idx];
    float iz = 1.0f / z;
    g_u2[idx] = make_float2(g_E2[idx] * iz, g_E2p[idx] * iz);
}

// ============================================================
// attgemm v4: fp16 single-pass. block = 64i x 256o, 256 thr, 2 CTA/SM.
// double-buffered cp.async B + register-prefetched adj/u2.
// grid (32 itile, 8 b) = 256 blocks.
// ============================================================
#define ST_A   0
#define ST_B   5120
#define STAGE  25600

__device__ __forceinline__ void genA(uint32 stg, const int2* radj, float4 ru2,
                                     int ibase, int jp, const float2* E)
{
    #pragma unroll
    for (int it = 0; it < 4; it++) {
        float q0 = fmaxf(E[it].x * ru2.x, E[it].y * ru2.y);
        float q1 = fmaxf(E[it].x * ru2.z, E[it].y * ru2.w);
        float w0 = radj[it].x ? q0 : 0.f;
        float w1 = radj[it].y ? q1 : 0.f;
        sts32(stg + ST_A + (uint32)(ibase + it*16) * PITCH + jp * 4, pack_f16x2(w0, w1));
    }
}

__global__ __launch_bounds__(256,2) void attgemm_mma(
    const int* __restrict__ adj, float* __restrict__ out)
{
    extern __shared__ __align__(16) unsigned char dsm[];
    __shared__ float2 sE1[64];
    const uint32 sb = smem_u32(dsm);
    const int tid = threadIdx.x, lane = tid & 31, wid = tid >> 5;
    const int b = blockIdx.y, i0 = blockIdx.x * 64;
    const int iw = (wid & 1) * 32, ow = (wid >> 1) * 64;

    if (tid < 64)
        sE1[tid] = make_float2(g_E1[b*NN + i0 + tid], g_E1p[b*NN + i0 + tid]);

    float c[2][8][4];
    #pragma unroll
    for (int x = 0; x < 2; x++)
        #pragma unroll
        for (int y = 0; y < 8; y++)
            #pragma unroll
            for (int d = 0; d < 4; d++) c[x][y][d] = 0.f;

    const int jp    = tid & 15;      // 16 j-pairs (32 j per chunk)
    const int ibase = tid >> 4;      // 0..15; i = ibase + it*16
    uint32 bdst[4]; const uint4* bsrc[4];
    #pragma unroll
    for (int p = 0; p < 4; p++) {
        int q = tid + p * 256;            // 0..1023 = 256 o x 4 seg
        int o = q >> 2, seg = q & 3;
        bdst[p] = ST_B + (uint32)o * PITCH + (uint32)seg * 16;
        bsrc[p] = (const uint4*)g_hT16 + (size_t)(b*FF + o) * (NN/8) + seg;
    }
    const int2*   arow   = (const int2*)(adj + (size_t)(b*NN + i0) * NN);
    const float4* u2base = (const float4*)g_u2 + (size_t)(b*NN)/2;

    int2 radj[4]; float4 ru2; float2 E[4];

    // ---- prologue ----
    {
        #pragma unroll
        for (int p = 0; p < 4; p++) cpa16(sb + bdst[p], bsrc[p]);
        CPA_COMMIT();
        #pragma unroll
        for (int it = 0; it < 4; it++)
            radj[it] = __ldg(&arow[(size_t)(ibase + it*16) * (NN/2) + jp]);
        ru2 = __ldg(&u2base[jp]);
        __syncthreads();                  // sE1 ready
        #pragma unroll
        for (int it = 0; it < 4; it++) E[it] = sE1[ibase + it*16];
        genA(sb, radj, ru2, ibase, jp, E);
        CPA_WAIT0();
        __syncthreads();
    }

    for (int cc = 0; cc < 64; cc++) {
        const int s = cc & 1;
        const uint32 stg  = sb + (uint32)s * STAGE;
        const uint32 stg1 = sb + (uint32)(s ^ 1) * STAGE;
        if (cc < 63) {
            const int j1 = (cc + 1) * 32;
            #pragma unroll
            for (int p = 0; p < 4; p++) cpa16(stg1 + bdst[p], bsrc[p] + (j1 >> 3));
            CPA_COMMIT();
            #pragma unroll
            for (int it = 0; it < 4; it++)
                radj[it] = __ldg(&arow[(size_t)(ibase + it*16) * (NN/2) + (j1 >> 1) + jp]);
            ru2 = __ldg(&u2base[(j1 >> 1) + jp]);
        }
        mma_chunk_f16(c, stg + ST_A, stg + ST_B, iw, ow, lane);
        if (cc < 63) {
            genA(stg1, radj, ru2, ibase, jp, E);
            CPA_WAIT0();
        }
        __syncthreads();
    }

    // ---- epilogue: ELU + store ----
    const int g = lane >> 2, cq = (lane & 3) * 2;
    #pragma unroll
    for (int mt = 0; mt < 2; mt++)
        #pragma unroll
        for (int nt = 0; nt < 8; nt++) {
            int i = i0 + iw + mt*16 + g;
            int o = ow + nt*8 + cq;
            float f0 = c[mt][nt][0], f1 = c[mt][nt][1];
            float f2 = c[mt][nt][2], f3 = c[mt][nt][3];
            f0 = f0 > 0.f ? f0 : expm1f(f0);
            f1 = f1 > 0.f ? f1 : expm1f(f1);
            f2 = f2 > 0.f ? f2 : expm1f(f2);
            f3 = f3 > 0.f ? f3 : expm1f(f3);
            *(float2*)&out[((size_t)(b*NN + i))   * FF + o] = make_float2(f0, f1);
            *(float2*)&out[((size_t)(b*NN + i+8)) * FF + o] = make_float2(f2, f3);
        }
}

extern "C" void kernel_launch(void* const* d_in, const int* in_sizes, int n_in,
                              void* d_out, int out_size)
{
    const float* x   = (const float*)d_in[0];
    const int*   adj = (const int*)d_in[1];
    const float* W   = (const float*)d_in[2];
    const float* a   = (const float*)d_in[3];
    float* out = (float*)d_out;

    cudaFuncSetAttribute(attgemm_mma, cudaFuncAttributeMaxDynamicSharedMemorySize, 2*STAGE);

    xsplit_kernel<<<1024, 256>>>(x);
    wsplitT_kernel<<<128, 256>>>(W);
    gemm1_mma<<<dim3(2, 128), 256>>>();
    s_kernel<<<2048, 256>>>(a);
    hsplit_kernel<<<dim3(32, 8, 8), 256>>>();
    zpass_kernel<<<dim3(2, 32, 8), 256>>>(adj);
    zreduce_kernel<<<64, 256>>>();
    attgemm_mma<<<dim3(32, 8), 256, 2*STAGE>>>(adj, out);
}

// round 7
// speedup vs baseline: 3.7302x; 1.0882x over previous
#include <cuda_runtime.h>
#include <cuda_bf16.h>
#include <cuda_fp16.h>

typedef unsigned int uint32;

#define BB 8
#define NN 2048
#define FF 256
#define M_TOT (BB*NN)   // 16384
#define PITCH 80        // bytes per SMEM tile row (conflict-free ldmatrix)

// ---- scratch (device globals; no runtime allocations) ----
__device__ float g_E1[M_TOT], g_E1p[M_TOT], g_E2[M_TOT], g_E2p[M_TOT];
__device__ float g_s1p[2*M_TOT], g_s2p[2*M_TOT];
__device__ __align__(16) float g_Zp[32*M_TOT];             // 2 MB partials
__device__ __align__(16) float2 g_u2[M_TOT];               // (E2*invZ, E2p*invZ)
// h^T fp16, [b][o][pair]: pair p of group grp packs (j, j+8), j = grp*16 + p
__device__ __align__(16) unsigned int g_hT16[M_TOT*FF/2];  // 8 MB
__device__ __align__(16) unsigned int g_WTh[FF*FF/2];      // W^T bf16 hi, [n][k-pairs]
__device__ __align__(16) unsigned int g_WTl[FF*FF/2];

// ================= helpers =================
__device__ __forceinline__ uint32 smem_u32(const void* p){
    uint32 a; asm("{ .reg .u64 t; cvta.to.shared.u64 t, %1; cvt.u32.u64 %0, t; }" : "=r"(a) : "l"(p));
    return a;
}
__device__ __forceinline__ uint32 pack_bf2(float a, float b){
    uint32 r; asm("cvt.rn.bf16x2.f32 %0, %1, %2;" : "=r"(r) : "f"(b), "f"(a)); return r;
}
__device__ __forceinline__ uint32 pack_f16x2(float a, float b){
    uint32 r; asm("cvt.rn.f16x2.f32 %0, %1, %2;" : "=r"(r) : "f"(b), "f"(a)); return r;
}
__device__ __forceinline__ void sts32(uint32 addr, uint32 v){
    asm volatile("st.shared.b32 [%0], %1;" :: "r"(addr), "r"(v) : "memory");
}
__device__ __forceinline__ void sts64(uint32 addr, uint32 a, uint32 b){
    asm volatile("st.shared.v2.b32 [%0], {%1,%2};" :: "r"(addr), "r"(a), "r"(b) : "memory");
}
__device__ __forceinline__ void sts128(uint32 addr, uint4 v){
    asm volatile("st.shared.v4.b32 [%0], {%1,%2,%3,%4};"
        :: "r"(addr), "r"(v.x), "r"(v.y), "r"(v.z), "r"(v.w) : "memory");
}
__device__ __forceinline__ void ldm4(uint32* r, uint32 addr){
    asm volatile("ldmatrix.sync.aligned.m8n8.x4.shared.b16 {%0,%1,%2,%3}, [%4];"
        : "=r"(r[0]), "=r"(r[1]), "=r"(r[2]), "=r"(r[3]) : "r"(addr));
}
__device__ __forceinline__ void mma_bf16(float* c, const uint32* a, uint32 b0, uint32 b1){
    asm volatile("mma.sync.aligned.m16n8k16.row.col.f32.bf16.bf16.f32 "
        "{%0,%1,%2,%3}, {%4,%5,%6,%7}, {%8,%9}, {%0,%1,%2,%3};"
        : "+f"(c[0]), "+f"(c[1]), "+f"(c[2]), "+f"(c[3])
        : "r"(a[0]), "r"(a[1]), "r"(a[2]), "r"(a[3]), "r"(b0), "r"(b1));
}
__device__ __forceinline__ void mma_f16(float* c, const uint32* a, uint32 b0, uint32 b1){
    asm volatile("mma.sync.aligned.m16n8k16.row.col.f32.f16.f16.f32 "
        "{%0,%1,%2,%3}, {%4,%5,%6,%7}, {%8,%9}, {%0,%1,%2,%3};"
        : "+f"(c[0]), "+f"(c[1]), "+f"(c[2]), "+f"(c[3])
        : "r"(a[0]), "r"(a[1]), "r"(a[2]), "r"(a[3]), "r"(b0), "r"(b1));
}
__device__ __forceinline__ void cpa16(uint32 dst, const void* src){
    asm volatile("cp.async.cg.shared.global [%0], [%1], 16;" :: "r"(dst), "l"(src) : "memory");
}
#define CPA_COMMIT() asm volatile("cp.async.commit_group;" ::: "memory")
#define CPA_WAIT0()  asm volatile("cp.async.wait_group 0;" ::: "memory")

__device__ __forceinline__ void split_pair(float v0, float v1, uint32& hi, uint32& lo){
    hi = pack_bf2(v0, v1);
    float l0 = v0 - __uint_as_float(hi << 16);
    float l1 = v1 - __uint_as_float(hi & 0xFFFF0000u);
    lo = pack_bf2(l0, l1);
}

// ---- bf16 3-pass MMA core (gemm1) ----
__device__ __forceinline__ void mma_chunk(float c[2][8][4],
    uint32 Ah, uint32 Al, uint32 Bh, uint32 Bl, int iw, int ow, int lane)
{
    const uint32 base_off = (uint32)(lane & 15) * PITCH + (uint32)(lane >> 4) * 16;
    #pragma unroll
    for (int ks = 0; ks < 2; ks++) {
        const uint32 off = base_off + ks * 32;
        uint32 A0[4], A1[4], A0l[4], A1l[4], B[4][4];
        ldm4(A0, Ah + (uint32)iw * PITCH + off);
        ldm4(A1, Ah + (uint32)(iw + 16) * PITCH + off);
        #pragma unroll
        for (int t = 0; t < 4; t++) ldm4(B[t], Bh + (uint32)(ow + t*16) * PITCH + off);
        #pragma unroll
        for (int t = 0; t < 4; t++) {
            mma_bf16(c[0][t*2+0], A0, B[t][0], B[t][2]);
            mma_bf16(c[1][t*2+0], A1, B[t][0], B[t][2]);
            mma_bf16(c[0][t*2+1], A0, B[t][1], B[t][3]);
            mma_bf16(c[1][t*2+1], A1, B[t][1], B[t][3]);
        }
        ldm4(A0l, Al + (uint32)iw * PITCH + off);
        ldm4(A1l, Al + (uint32)(iw + 16) * PITCH + off);
        #pragma unroll
        for (int t = 0; t < 4; t++) {
            mma_bf16(c[0][t*2+0], A0l, B[t][0], B[t][2]);
            mma_bf16(c[1][t*2+0], A1l, B[t][0], B[t][2]);
            mma_bf16(c[0][t*2+1], A0l, B[t][1], B[t][3]);
            mma_bf16(c[1][t*2+1], A1l, B[t][1], B[t][3]);
        }
        #pragma unroll
        for (int t = 0; t < 4; t++) ldm4(B[t], Bl + (uint32)(ow + t*16) * PITCH + off);
        #pragma unroll
        for (int t = 0; t < 4; t++) {
            mma_bf16(c[0][t*2+0], A0, B[t][0], B[t][2]);
            mma_bf16(c[1][t*2+0], A1, B[t][0], B[t][2]);
            mma_bf16(c[0][t*2+1], A0, B[t][1], B[t][3]);
            mma_bf16(c[1][t*2+1], A1, B[t][1], B[t][3]);
        }
    }
}

// ---- fp16 single-pass MMA core (attgemm) ----
__device__ __forceinline__ void mma_chunk_f16(float c[2][8][4],
    uint32 A, uint32 B, int iw, int ow, int lane)
{
    const uint32 base_off = (uint32)(lane & 15) * PITCH + (uint32)(lane >> 4) * 16;
    #pragma unroll
    for (int ks = 0; ks < 2; ks++) {
        const uint32 off = base_off + ks * 32;
        uint32 A0[4], A1[4], Bt[4][4];
        ldm4(A0, A + (uint32)iw * PITCH + off);
        ldm4(A1, A + (uint32)(iw + 16) * PITCH + off);
        #pragma unroll
        for (int t = 0; t < 4; t++) ldm4(Bt[t], B + (uint32)(ow + t*16) * PITCH + off);
        #pragma unroll
        for (int t = 0; t < 4; t++) {
            mma_f16(c[0][t*2+0], A0, Bt[t][0], Bt[t][2]);
            mma_f16(c[1][t*2+0], A1, Bt[t][0], Bt[t][2]);
            mma_f16(c[0][t*2+1], A0, Bt[t][1], Bt[t][3]);
            mma_f16(c[1][t*2+1], A1, Bt[t][1], Bt[t][3]);
        }
    }
}

// ============================================================
// wsplitT: W [k][n] fp32 -> W^T bf16 hi/lo [n][k/2]
// ============================================================
__global__ void wsplitT_kernel(const float* __restrict__ W)
{
    int idx = blockIdx.x * 256 + threadIdx.x;
    int n = idx >> 7, kp = idx & 127;
    float v0 = W[(size_t)(2*kp)   * FF + n];
    float v1 = W[(size_t)(2*kp+1) * FF + n];
    uint32 hi, lo; split_pair(v0, v1, hi, lo);
    g_WTh[n*128 + kp] = hi; g_WTl[n*128 + kp] = lo;
}

// ============================================================
// gemm1_fused: h = x @ W (bf16 3-pass); epilogue emits hT16 (permuted
// stride-8 pairs) + s1/s2 partial dots. No fp32 h anywhere.
// grid (2 ntile, 128 mtile), 256 thr.
// ============================================================
__global__ __launch_bounds__(256,2) void gemm1_fused(
    const float* __restrict__ x, const float* __restrict__ a)
{
    __shared__ __align__(16) unsigned char smA[2][128*PITCH];
    __shared__ __align__(16) unsigned char smB[2][128*PITCH];
    const uint32 Ah = smem_u32(smA[0]), Al = smem_u32(smA[1]);
    const uint32 Bh = smem_u32(smB[0]), Bl = smem_u32(smB[1]);
    const int tid = threadIdx.x, lane = tid & 31, wid = tid >> 5;
    const int m0 = blockIdx.y * 128, n0 = blockIdx.x * 128;
    const int iw = (wid & 3) * 32, ow = (wid >> 2) * 64;

    float c[2][8][4];
    #pragma unroll
    for (int u = 0; u < 2; u++)
        #pragma unroll
        for (int v = 0; v < 8; v++)
            #pragma unroll
            for (int d = 0; d < 4; d++) c[u][v][d] = 0.f;

    const uint4* wh = (const uint4*)g_WTh; const uint4* wl = (const uint4*)g_WTl;

    for (int kt = 0; kt < 256; kt += 32) {
        __syncthreads();
        // x fp32 -> bf16 hi/lo split, staged to smem (fused xsplit)
        #pragma unroll
        for (int p = 0; p < 4; p++) {
            int q = tid + p * 256;        // 0..1023 float4-quads
            int row = q >> 3, f4 = q & 7;
            float4 v = *(const float4*)&x[(size_t)(m0 + row) * 256 + kt + f4*4];
            uint32 h0, l0, h1, l1;
            split_pair(v.x, v.y, h0, l0);
            split_pair(v.z, v.w, h1, l1);
            uint32 off = (uint32)row * PITCH + f4 * 8;
            sts64(Ah + off, h0, h1);
            sts64(Al + off, l0, l1);
        }
        #pragma unroll
        for (int p = 0; p < 2; p++) {
            int q = tid + p * 256;
            int row = q >> 2, seg = q & 3;
            uint32 off = (uint32)row * PITCH + seg * 16;
            size_t gi = (size_t)(n0 + row) * 32 + (kt >> 3) + seg;
            sts128(Bh + off, wh[gi]);
            sts128(Bl + off, wl[gi]);
        }
        __syncthreads();
        mma_chunk(c, Ah, Al, Bh, Bl, iw, ow, lane);
    }

    // ---- epilogue: hT16 (stride-8 pair packing, direct from regs) + s-partials ----
    const int g = lane >> 2, cq = (lane & 3) * 2;
    const int bb = m0 >> 11;
    const int jb = (m0 & 2047) + iw;
    float s1a[4] = {0.f,0.f,0.f,0.f}, s2a[4] = {0.f,0.f,0.f,0.f};
    #pragma unroll
    for (int mt = 0; mt < 2; mt++) {
        uint32 pidx = (uint32)((jb + mt*16) >> 4) * 8 + g;
        #pragma unroll
        for (int nt = 0; nt < 8; nt++) {
            int n = n0 + ow + nt*8 + cq;   // global o
            float c0 = c[mt][nt][0], c1 = c[mt][nt][1];
            float c2 = c[mt][nt][2], c3 = c[mt][nt][3];
            float a10 = __ldg(&a[n]),       a11 = __ldg(&a[n+1]);
            float a20 = __ldg(&a[256 + n]), a21 = __ldg(&a[256 + n + 1]);
            s1a[mt*2+0] += c0*a10 + c1*a11;
            s1a[mt*2+1] += c2*a10 + c3*a11;
            s2a[mt*2+0] += c0*a20 + c1*a21;
            s2a[mt*2+1] += c2*a20 + c3*a21;
            g_hT16[((size_t)(bb*FF + n))   * 1024 + pidx] = pack_f16x2(c0, c2);
            g_hT16[((size_t)(bb*FF + n+1)) * 1024 + pidx] = pack_f16x2(c1, c3);
        }
    }
    // deterministic slot-based s reduction (reuse smA as scratch)
    __syncthreads();
    float* sS1 = (float*)smA[0];
    float* sS2 = sS1 + 1024;
    const int slot = (wid >> 2) * 4 + (lane & 3);
    sS1[(iw + g)      * 8 + slot] = s1a[0];
    sS1[(iw + g + 8)  * 8 + slot] = s1a[1];
    sS1[(iw + g + 16) * 8 + slot] = s1a[2];
    sS1[(iw + g + 24) * 8 + slot] = s1a[3];
    sS2[(iw + g)      * 8 + slot] = s2a[0];
    sS2[(iw + g + 8)  * 8 + slot] = s2a[1];
    sS2[(iw + g + 16) * 8 + slot] = s2a[2];
    sS2[(iw + g + 24) * 8 + slot] = s2a[3];
    __syncthreads();
    int m = tid & 127;
    const float* arr = (tid < 128) ? sS1 : sS2;
    float s = 0.f;
    #pragma unroll
    for (int k2 = 0; k2 < 8; k2++) s += arr[m*8 + k2];
    float* dst = (tid < 128) ? g_s1p : g_s2p;
    dst[(size_t)blockIdx.x * M_TOT + m0 + m] = s;
}

// ============================================================
// sexp: finish s1/s2 reduction + exp tables
// ============================================================
__global__ void sexp_kernel()
{
    int idx = blockIdx.x * 256 + threadIdx.x;
    float s1 = g_s1p[idx] + g_s1p[M_TOT + idx];
    float s2 = g_s2p[idx] + g_s2p[M_TOT + idx];
    g_E1[idx]  = __expf(s1);        g_E1p[idx] = __expf(0.2f * s1);
    g_E2[idx]  = __expf(s2);        g_E2p[idx] = __expf(0.2f * s2);
}

// ============================================================
// zpass: Z[b,j] = e_j * sum_i adj * max(E1_i, r_j*E1p_i),  r_j = ep_j/e_j
// grid (2 jchunk, 32 iseg, 8 b) = 512 blocks, 256 thr, 4 j/thread
// ============================================================
__global__ __launch_bounds__(256) void zpass_kernel(const int* __restrict__ adj)
{
    __shared__ float2 sE[64];
    const int b = blockIdx.z, iseg = blockIdx.y, tid = threadIdx.x;
    const int j = blockIdx.x * 1024 + tid * 4;
    const int ibase = iseg * 64;
    if (tid < 64)
        sE[tid] = make_float2(g_E1[b*NN + ibase + tid], g_E1p[b*NN + ibase + tid]);
    __syncthreads();
    float e0 = __ldg(&g_E2[b*NN+j]),   e1 = __ldg(&g_E2[b*NN+j+1]);
    float e2 = __ldg(&g_E2[b*NN+j+2]), e3 = __ldg(&g_E2[b*NN+j+3]);
    float r0 = __ldg(&g_E2p[b*NN+j])   / e0, r1 = __ldg(&g_E2p[b*NN+j+1]) / e1;
    float r2 = __ldg(&g_E2p[b*NN+j+2]) / e2, r3 = __ldg(&g_E2p[b*NN+j+3]) / e3;
    const int4* ap = (const int4*)(adj + (size_t)(b*NN + ibase) * NN) + (j >> 2);
    float z0=0.f, z1=0.f, z2=0.f, z3=0.f;
    #pragma unroll 8
    for (int il = 0; il < 64; il++) {
        int4 av = __ldg(&ap[(size_t)il * (NN/4)]);
        float2 E = sE[il];
        float q0 = fmaxf(E.x, r0*E.y);
        float q1 = fmaxf(E.x, r1*E.y);
        float q2 = fmaxf(E.x, r2*E.y);
        float q3 = fmaxf(E.x, r3*E.y);
        if (av.x) z0 += q0;
        if (av.y) z1 += q1;
        if (av.z) z2 += q2;
        if (av.w) z3 += q3;
    }
    *(float4*)&g_Zp[(size_t)iseg * M_TOT + b*NN + j] = make_float4(z0*e0, z1*e1, z2*e2, z3*e3);
}

__global__ void zreduce_kernel()
{
    int idx = blockIdx.x * 256 + threadIdx.x;
    float z = 0.f;
    #pragma unroll
    for (int s = 0; s < 32; s++) z += g_Zp[(size_t)s * M_TOT + idx];
    float iz = 1.0f / z;
    g_u2[idx] = make_float2(g_E2[idx] * iz, g_E2p[idx] * iz);
}

// ============================================================
// attgemm: fp16 single-pass. block = 64i x 256o, 256 thr, 2 CTA/SM.
// double-buffered cp.async B + register-prefetched adj/u2.
// A generated with the SAME stride-8 j-permutation as hT16 packing.
// grid (32 itile, 8 b).
// ============================================================
#define ST_A   0
#define ST_B   5120
#define STAGE  25600

__device__ __forceinline__ void genA(uint32 stg, const int* alo, const int* ahi,
                                     float2 ulo, float2 uhi,
                                     int ibase, int jp, const float2* E)
{
    #pragma unroll
    for (int it = 0; it < 4; it++) {
        float wl = alo[it] ? fmaxf(E[it].x * ulo.x, E[it].y * ulo.y) : 0.f;
        float wh = ahi[it] ? fmaxf(E[it].x * uhi.x, E[it].y * uhi.y) : 0.f;
        sts32(stg + ST_A + (uint32)(ibase + it*16) * PITCH + jp * 4, pack_f16x2(wl, wh));
    }
}

__global__ __launch_bounds__(256,2) void attgemm_mma(
    const int* __restrict__ adj, float* __restrict__ out)
{
    extern __shared__ __align__(16) unsigned char dsm[];
    __shared__ float2 sE1[64];
    const uint32 sb = smem_u32(dsm);
    const int tid = threadIdx.x, lane = tid & 31, wid = tid >> 5;
    const int b = blockIdx.y, i0 = blockIdx.x * 64;
    const int iw = (wid & 1) * 32, ow = (wid >> 1) * 64;

    if (tid < 64)
        sE1[tid] = make_float2(g_E1[b*NN + i0 + tid], g_E1p[b*NN + i0 + tid]);

    float c[2][8][4];
    #pragma unroll
    for (int u = 0; u < 2; u++)
        #pragma unroll
        for (int v = 0; v < 8; v++)
            #pragma unroll
            for (int d = 0; d < 4; d++) c[u][v][d] = 0.f;

    const int jp    = tid & 15;                       // word index 0..15
    const int joff  = (jp & 7) | ((jp >> 3) << 4);    // permuted j offset (lo)
    const int ibase = tid >> 4;                       // 0..15; i = ibase + it*16
    uint32 bdst[4]; const uint4* bsrc[4];
    #pragma unroll
    for (int p = 0; p < 4; p++) {
        int q = tid + p * 256;            // 0..1023 = 256 o x 4 seg
        int o = q >> 2, seg = q & 3;
        bdst[p] = ST_B + (uint32)o * PITCH + (uint32)seg * 16;
        bsrc[p] = (const uint4*)g_hT16 + (size_t)(b*FF + o) * (NN/8) + seg;
    }
    const int*    arow = adj + (size_t)(b*NN + i0) * NN;
    const float2* u2b  = g_u2 + (size_t)b * NN;

    int alo[4], ahi[4]; float2 ulo, uhi; float2 E[4];

    // ---- prologue ----
    {
        #pragma unroll
        for (int p = 0; p < 4; p++) cpa16(sb + bdst[p], bsrc[p]);
        CPA_COMMIT();
        #pragma unroll
        for (int it = 0; it < 4; it++) {
            size_t base = (size_t)(ibase + it*16) * NN + joff;
            alo[it] = __ldg(&arow[base]);
            ahi[it] = __ldg(&arow[base + 8]);
        }
        ulo = __ldg(&u2b[joff]);
        uhi = __ldg(&u2b[joff + 8]);
        __syncthreads();                  // sE1 ready
        #pragma unroll
        for (int it = 0; it < 4; it++) E[it] = sE1[ibase + it*16];
        genA(sb, alo, ahi, ulo, uhi, ibase, jp, E);
        CPA_WAIT0();
        __syncthreads();
    }

    for (int cc = 0; cc < 64; cc++) {
        const int s = cc & 1;
        const uint32 stg  = sb + (uint32)s * STAGE;
        const uint32 stg1 = sb + (uint32)(s ^ 1) * STAGE;
        if (cc < 63) {
            const int j1 = (cc + 1) * 32;
            #pragma unroll
            for (int p = 0; p < 4; p++) cpa16(stg1 + bdst[p], bsrc[p] + (j1 >> 3));
            CPA_COMMIT();
            #pragma unroll
            for (int it = 0; it < 4; it++) {
                size_t base = (size_t)(ibase + it*16) * NN + j1 + joff;
                alo[it] = __ldg(&arow[base]);
                ahi[it] = __ldg(&arow[base + 8]);
            }
            ulo = __ldg(&u2b[j1 + joff]);
            uhi = __ldg(&u2b[j1 + joff + 8]);
        }
        mma_chunk_f16(c, stg + ST_A, stg + ST_B, iw, ow, lane);
        if (cc < 63) {
            genA(stg1, alo, ahi, ulo, uhi, ibase, jp, E);
            CPA_WAIT0();
        }
        __syncthreads();
    }

    // ---- epilogue: ELU + store ----
    const int g = lane >> 2, cq = (lane & 3) * 2;
    #pragma unroll
    for (int mt = 0; mt < 2; mt++)
        #pragma unroll
        for (int nt = 0; nt < 8; nt++) {
            int i = i0 + iw + mt*16 + g;
            int o = ow + nt*8 + cq;
            float f0 = c[mt][nt][0], f1 = c[mt][nt][1];
            float f2 = c[mt][nt][2], f3 = c[mt][nt][3];
            f0 = f0 > 0.f ? f0 : expm1f(f0);
            f1 = f1 > 0.f ? f1 : expm1f(f1);
            f2 = f2 > 0.f ? f2 : expm1f(f2);
            f3 = f3 > 0.f ? f3 : expm1f(f3);
            *(float2*)&out[((size_t)(b*NN + i))   * FF + o] = make_float2(f0, f1);
            *(float2*)&out[((size_t)(b*NN + i+8)) * FF + o] = make_float2(f2, f3);
        }
}

extern "C" void kernel_launch(void* const* d_in, const int* in_sizes, int n_in,
                              void* d_out, int out_size)
{
    const float* x   = (const float*)d_in[0];
    const int*   adj = (const int*)d_in[1];
    const float* W   = (const float*)d_in[2];
    const float* a   = (const float*)d_in[3];
    float* out = (float*)d_out;

    cudaFuncSetAttribute(attgemm_mma, cudaFuncAttributeMaxDynamicSharedMemorySize, 2*STAGE);

    wsplitT_kernel<<<128, 256>>>(W);
    gemm1_fused<<<dim3(2, 128), 256>>>(x, a);
    sexp_kernel<<<64, 256>>>();
    zpass_kernel<<<dim3(2, 32, 8), 256>>>(adj);
    zreduce_kernel<<<64, 256>>>();
    attgemm_mma<<<dim3(32, 8), 256, 2*STAGE>>>(adj, out);
}

// round 8
// speedup vs baseline: 4.2228x; 1.1321x over previous
#include <cuda_runtime.h>
#include <cuda_fp16.h>

typedef unsigned int uint32;

#define BB 8
#define NN 2048
#define FF 256
#define M_TOT (BB*NN)   // 16384
#define PITCH 80        // gemm1 tile pitch (32 fp16 cols)
#define PITCH2 144      // attgemm tile pitch (64 fp16 cols)

// ---- scratch (device globals; no runtime allocations) ----
__device__ float g_E1[M_TOT], g_E1p[M_TOT], g_E2[M_TOT], g_E2p[M_TOT];
__device__ float g_wa1[FF], g_wa2[FF];
__device__ __align__(16) float g_Zp[64*M_TOT];             // 4 MB partials
__device__ __align__(16) float2 g_u2[M_TOT];               // (E2*invZ, E2p*invZ)
// h^T fp16, [b][o][word]: word w of 16-group grp packs (j, j+8), j = grp*16 + (w&7)
__device__ __align__(16) unsigned int g_hT16[M_TOT*FF/2];  // 8 MB
__device__ __align__(16) unsigned int g_WT16[FF*FF/2];     // W^T fp16 [n][k-pairs]

// ================= helpers =================
__device__ __forceinline__ uint32 smem_u32(const void* p){
    uint32 a; asm("{ .reg .u64 t; cvta.to.shared.u64 t, %1; cvt.u32.u64 %0, t; }" : "=r"(a) : "l"(p));
    return a;
}
__device__ __forceinline__ uint32 pack_f16x2(float a, float b){
    uint32 r; asm("cvt.rn.f16x2.f32 %0, %1, %2;" : "=r"(r) : "f"(b), "f"(a)); return r;
}
__device__ __forceinline__ void sts32(uint32 addr, uint32 v){
    asm volatile("st.shared.b32 [%0], %1;" :: "r"(addr), "r"(v) : "memory");
}
__device__ __forceinline__ void sts64(uint32 addr, uint32 a, uint32 b){
    asm volatile("st.shared.v2.b32 [%0], {%1,%2};" :: "r"(addr), "r"(a), "r"(b) : "memory");
}
__device__ __forceinline__ void sts128(uint32 addr, uint4 v){
    asm volatile("st.shared.v4.b32 [%0], {%1,%2,%3,%4};"
        :: "r"(addr), "r"(v.x), "r"(v.y), "r"(v.z), "r"(v.w) : "memory");
}
__device__ __forceinline__ void ldm4(uint32* r, uint32 addr){
    asm volatile("ldmatrix.sync.aligned.m8n8.x4.shared.b16 {%0,%1,%2,%3}, [%4];"
        : "=r"(r[0]), "=r"(r[1]), "=r"(r[2]), "=r"(r[3]) : "r"(addr));
}
__device__ __forceinline__ void mma_f16(float* c, const uint32* a, uint32 b0, uint32 b1){
    asm volatile("mma.sync.aligned.m16n8k16.row.col.f32.f16.f16.f32 "
        "{%0,%1,%2,%3}, {%4,%5,%6,%7}, {%8,%9}, {%0,%1,%2,%3};"
        : "+f"(c[0]), "+f"(c[1]), "+f"(c[2]), "+f"(c[3])
        : "r"(a[0]), "r"(a[1]), "r"(a[2]), "r"(a[3]), "r"(b0), "r"(b1));
}
__device__ __forceinline__ void cpa16(uint32 dst, const void* src){
    asm volatile("cp.async.cg.shared.global [%0], [%1], 16;" :: "r"(dst), "l"(src) : "memory");
}
#define CPA_COMMIT() asm volatile("cp.async.commit_group;" ::: "memory")
#define CPA_WAIT0()  asm volatile("cp.async.wait_group 0;" ::: "memory")

// ============================================================
// wsplit16: W [k][n] fp32 -> W^T fp16 [n][k-pairs]
// ============================================================
__global__ void wsplit16_kernel(const float* __restrict__ W)
{
    int idx = blockIdx.x * 256 + threadIdx.x;   // 32768 words
    int n = idx >> 7, kp = idx & 127;
    float v0 = W[(size_t)(2*kp)   * FF + n];
    float v1 = W[(size_t)(2*kp+1) * FF + n];
    g_WT16[n*128 + kp] = pack_f16x2(v0, v1);
}

// ============================================================
// wa: Wa1[k] = sum_n W[k][n]*a1[n], Wa2 similarly (fp32 exact path)
// ============================================================
__global__ void wa_kernel(const float* __restrict__ W, const float* __restrict__ a)
{
    int w = threadIdx.x >> 5, lane = threadIdx.x & 31;
    int k = blockIdx.x * 8 + w;
    float s1 = 0.f, s2 = 0.f;
    #pragma unroll
    for (int q = 0; q < 8; q++) {
        int e = lane + 32 * q;
        float v = __ldg(&W[(size_t)k * FF + e]);
        s1 += v * __ldg(&a[e]);
        s2 += v * __ldg(&a[256 + e]);
    }
    #pragma unroll
    for (int o = 16; o > 0; o >>= 1) {
        s1 += __shfl_xor_sync(0xffffffffu, s1, o);
        s2 += __shfl_xor_sync(0xffffffffu, s2, o);
    }
    if (lane == 0) { g_wa1[k] = s1; g_wa2[k] = s2; }
}

// ============================================================
// sexp: s1[m] = x[m,:].Wa1 (fp32 exact), exp tables
// ============================================================
__global__ void sexp_kernel(const float* __restrict__ x)
{
    int warp = threadIdx.x >> 5, lane = threadIdx.x & 31;
    int row = blockIdx.x * 8 + warp;
    const float* xr = x + (size_t)row * FF;
    float s1 = 0.f, s2 = 0.f;
    #pragma unroll
    for (int q = 0; q < 8; q++) {
        int e = lane + 32 * q;
        float v = xr[e];
        s1 += v * __ldg(&g_wa1[e]);
        s2 += v * __ldg(&g_wa2[e]);
    }
    #pragma unroll
    for (int o = 16; o > 0; o >>= 1) {
        s1 += __shfl_xor_sync(0xffffffffu, s1, o);
        s2 += __shfl_xor_sync(0xffffffffu, s2, o);
    }
    if (lane == 0) {
        g_E1[row]  = __expf(s1);        g_E1p[row] = __expf(0.2f * s1);
        g_E2[row]  = __expf(s2);        g_E2p[row] = __expf(0.2f * s2);
    }
}

// ============================================================
// gemm1: h = x @ W, single-pass fp16 HMMA; epilogue emits hT16
// (permuted stride-8 pairs) directly from accumulators.
// grid (2 ntile, 128 mtile), 256 thr.
// ============================================================
__global__ __launch_bounds__(256,2) void gemm1_f16(const float* __restrict__ x)
{
    __shared__ __align__(16) unsigned char smA[128*PITCH];
    __shared__ __align__(16) unsigned char smB[128*PITCH];
    const uint32 A = smem_u32(smA), B = smem_u32(smB);
    const int tid = threadIdx.x, lane = tid & 31, wid = tid >> 5;
    const int m0 = blockIdx.y * 128, n0 = blockIdx.x * 128;
    const int iw = (wid & 3) * 32, ow = (wid >> 2) * 64;

    float c[2][8][4];
    #pragma unroll
    for (int u = 0; u < 2; u++)
        #pragma unroll
        for (int v = 0; v < 8; v++)
            #pragma unroll
            for (int d = 0; d < 4; d++) c[u][v][d] = 0.f;

    const uint4* wt = (const uint4*)g_WT16;

    for (int kt = 0; kt < 256; kt += 32) {
        __syncthreads();
        // A: x fp32 -> fp16 in-register, staged
        #pragma unroll
        for (int p = 0; p < 4; p++) {
            int q = tid + p * 256;        // 1024 float4s
            int row = q >> 3, f4 = q & 7;
            float4 v = *(const float4*)&x[(size_t)(m0 + row) * 256 + kt + f4*4];
            sts64(A + (uint32)row * PITCH + f4 * 8,
                  pack_f16x2(v.x, v.y), pack_f16x2(v.z, v.w));
        }
        // B: W^T fp16 tile
        {
            int row = tid >> 1, seg = tid & 1;
            size_t gi = (size_t)(n0 + row) * 32 + (kt >> 3) + seg * 2;
            uint32 off = (uint32)row * PITCH + seg * 32;
            sts128(B + off,      wt[gi]);
            sts128(B + off + 16, wt[gi + 1]);
        }
        __syncthreads();
        // MMA: 2 ks x (2 A-ldsm + 4 B-ldsm + 16 HMMA)
        const uint32 base_off = (uint32)(lane & 15) * PITCH + (uint32)(lane >> 4) * 16;
        #pragma unroll
        for (int ks = 0; ks < 2; ks++) {
            const uint32 off = base_off + ks * 32;
            uint32 A0[4], A1[4], Bt[4][4];
            ldm4(A0, A + (uint32)iw * PITCH + off);
            ldm4(A1, A + (uint32)(iw + 16) * PITCH + off);
            #pragma unroll
            for (int t = 0; t < 4; t++) ldm4(Bt[t], B + (uint32)(ow + t*16) * PITCH + off);
            #pragma unroll
            for (int t = 0; t < 4; t++) {
                mma_f16(c[0][t*2+0], A0, Bt[t][0], Bt[t][2]);
                mma_f16(c[1][t*2+0], A1, Bt[t][0], Bt[t][2]);
                mma_f16(c[0][t*2+1], A0, Bt[t][1], Bt[t][3]);
                mma_f16(c[1][t*2+1], A1, Bt[t][1], Bt[t][3]);
            }
        }
    }

    // epilogue: hT16 stride-8 pair packing, direct from regs
    const int g = lane >> 2, cq = (lane & 3) * 2;
    const int bb = m0 >> 11;
    const int jb = (m0 & 2047) + iw;
    #pragma unroll
    for (int mt = 0; mt < 2; mt++) {
        uint32 pidx = (uint32)((jb + mt*16) >> 4) * 8 + g;
        #pragma unroll
        for (int nt = 0; nt < 8; nt++) {
            int n = n0 + ow + nt*8 + cq;
            g_hT16[((size_t)(bb*FF + n))   * 1024 + pidx] = pack_f16x2(c[mt][nt][0], c[mt][nt][2]);
            g_hT16[((size_t)(bb*FF + n+1)) * 1024 + pidx] = pack_f16x2(c[mt][nt][1], c[mt][nt][3]);
        }
    }
}

// ============================================================
// zpass: Z[b,j] = e_j * sum_i adj * max(E1_i, r_j*E1p_i)
// grid (2 jchunk, 64 iseg, 8 b) = 1024 blocks, 256 thr, 4 j/thread
// ============================================================
__global__ __launch_bounds__(256) void zpass_kernel(const int* __restrict__ adj)
{
    __shared__ float2 sE[32];
    const int b = blockIdx.z, iseg = blockIdx.y, tid = threadIdx.x;
    const int j = blockIdx.x * 1024 + tid * 4;
    const int ibase = iseg * 32;
    if (tid < 32)
        sE[tid] = make_float2(g_E1[b*NN + ibase + tid], g_E1p[b*NN + ibase + tid]);
    __syncthreads();
    float e0 = __ldg(&g_E2[b*NN+j]),   e1 = __ldg(&g_E2[b*NN+j+1]);
    float e2 = __ldg(&g_E2[b*NN+j+2]), e3 = __ldg(&g_E2[b*NN+j+3]);
    float r0 = __ldg(&g_E2p[b*NN+j])   / e0, r1 = __ldg(&g_E2p[b*NN+j+1]) / e1;
    float r2 = __ldg(&g_E2p[b*NN+j+2]) / e2, r3 = __ldg(&g_E2p[b*NN+j+3]) / e3;
    const int4* ap = (const int4*)(adj + (size_t)(b*NN + ibase) * NN) + (j >> 2);
    float z0=0.f, z1=0.f, z2=0.f, z3=0.f;
    #pragma unroll 8
    for (int il = 0; il < 32; il++) {
        int4 av = __ldg(&ap[(size_t)il * (NN/4)]);
        float2 E = sE[il];
        float q0 = fmaxf(E.x, r0*E.y);
        float q1 = fmaxf(E.x, r1*E.y);
        float q2 = fmaxf(E.x, r2*E.y);
        float q3 = fmaxf(E.x, r3*E.y);
        if (av.x) z0 += q0;
        if (av.y) z1 += q1;
        if (av.z) z2 += q2;
        if (av.w) z3 += q3;
    }
    *(float4*)&g_Zp[(size_t)iseg * M_TOT + b*NN + j] = make_float4(z0*e0, z1*e1, z2*e2, z3*e3);
}

__global__ void zreduce_kernel()
{
    int idx = blockIdx.x * 256 + threadIdx.x;
    float z = 0.f;
    #pragma unroll
    for (int s = 0; s < 64; s++) z += g_Zp[(size_t)s * M_TOT + idx];
    float iz = 1.0f / z;
    g_u2[idx] = make_float2(g_E2[idx] * iz, g_E2p[idx] * iz);
}

// ============================================================
// attgemm: fp16 single-pass, BJ=64 chunks. block = 64i x 256o,
// 256 thr, 2 CTA/SM, double-buffered cp.async B, on-the-fly A.
// grid (32 itile, 8 b).
// ============================================================
#define ST_B   9216
#define STAGE  46080

__global__ __launch_bounds__(256,2) void attgemm_mma(
    const int* __restrict__ adj, float* __restrict__ out)
{
    extern __shared__ __align__(16) unsigned char dsm[];
    __shared__ float2 sE1[64];
    const uint32 sb = smem_u32(dsm);
    const int tid = threadIdx.x, lane = tid & 31, wid = tid >> 5;
    const int b = blockIdx.y, i0 = blockIdx.x * 64;
    const int iw = (wid & 1) * 32, ow = (wid >> 1) * 64;

    if (tid < 64)
        sE1[tid] = make_float2(g_E1[b*NN + i0 + tid], g_E1p[b*NN + i0 + tid]);

    float c[2][8][4];
    #pragma unroll
    for (int u = 0; u < 2; u++)
        #pragma unroll
        for (int v = 0; v < 8; v++)
            #pragma unroll
            for (int d = 0; d < 4; d++) c[u][v][d] = 0.f;

    // per-thread fixed coordinates
    const int jp   = tid & 31;                        // word col 0..31
    const int joff = ((jp >> 3) << 4) | (jp & 7);     // logical j offset (lo of pair)
    const int irow = tid >> 5;                        // 0..7; i = irow + it*8
    const uint32 adst = (uint32)irow * PITCH2 + jp * 4;
    // B cp.async: o = tid>>3 + p*32, seg = tid&7
    const uint4* bbase = (const uint4*)g_hT16 + ((size_t)(b*FF + (tid >> 3))) * 256 + (tid & 7);
    const uint32 bd0 = ST_B + (uint32)(tid >> 3) * PITCH2 + (uint32)(tid & 7) * 16;
    const int*    arow = adj + (size_t)(b*NN + i0) * NN + joff;
    const float2* u2b  = g_u2 + (size_t)b * NN + joff;

    int alo[8], ahi[8]; float2 ulo, uhi;

    // ---- prologue: chunk 0 into buffer 0 ----
    {
        #pragma unroll
        for (int p = 0; p < 8; p++) cpa16(sb + bd0 + p*4608, bbase + p*8192);
        CPA_COMMIT();
        #pragma unroll
        for (int it = 0; it < 8; it++) {
            size_t base = (size_t)(irow + it*8) * NN;
            alo[it] = __ldg(&arow[base]);
            ahi[it] = __ldg(&arow[base + 8]);
        }
        ulo = __ldg(&u2b[0]);
        uhi = __ldg(&u2b[8]);
        __syncthreads();                  // sE1 ready
        #pragma unroll
        for (int it = 0; it < 8; it++) {
            float2 E = sE1[irow + it*8];
            float wl = alo[it] ? fmaxf(E.x * ulo.x, E.y * ulo.y) : 0.f;
            float wh = ahi[it] ? fmaxf(E.x * uhi.x, E.y * uhi.y) : 0.f;
            sts32(sb + adst + (uint32)(it*8) * PITCH2, pack_f16x2(wl, wh));
        }
        CPA_WAIT0();
        __syncthreads();
    }

    for (int cc = 0; cc < 32; cc++) {
        const int s = cc & 1;
        const uint32 stg  = sb + (uint32)s * STAGE;
        const uint32 stg1 = sb + (uint32)(s ^ 1) * STAGE;
        if (cc < 31) {
            const int j1 = (cc + 1) * 64;
            #pragma unroll
            for (int p = 0; p < 8; p++) cpa16(stg1 + bd0 + p*4608, bbase + p*8192 + (j1 >> 3));
            CPA_COMMIT();
            #pragma unroll
            for (int it = 0; it < 8; it++) {
                size_t base = (size_t)(irow + it*8) * NN + j1;
                alo[it] = __ldg(&arow[base]);
                ahi[it] = __ldg(&arow[base + 8]);
            }
            ulo = __ldg(&u2b[j1]);
            uhi = __ldg(&u2b[j1 + 8]);
        }
        // MMA over 64-wide chunk: 4 ks
        {
            const uint32 base_off = (uint32)(lane & 15) * PITCH2 + (uint32)(lane >> 4) * 16;
            #pragma unroll
            for (int ks = 0; ks < 4; ks++) {
                const uint32 off = base_off + ks * 32;
                uint32 A0[4], A1[4], Bt[4][4];
                ldm4(A0, stg + (uint32)iw * PITCH2 + off);
                ldm4(A1, stg + (uint32)(iw + 16) * PITCH2 + off);
                #pragma unroll
                for (int t = 0; t < 4; t++)
                    ldm4(Bt[t], stg + ST_B + (uint32)(ow + t*16) * PITCH2 + off);
                #pragma unroll
                for (int t = 0; t < 4; t++) {
                    mma_f16(c[0][t*2+0], A0, Bt[t][0], Bt[t][2]);
                    mma_f16(c[1][t*2+0], A1, Bt[t][0], Bt[t][2]);
                    mma_f16(c[0][t*2+1], A0, Bt[t][1], Bt[t][3]);
                    mma_f16(c[1][t*2+1], A1, Bt[t][1], Bt[t][3]);
                }
            }
        }
        if (cc < 31) {
            #pragma unroll
            for (int it = 0; it < 8; it++) {
                float2 E = sE1[irow + it*8];
                float wl = alo[it] ? fmaxf(E.x * ulo.x, E.y * ulo.y) : 0.f;
                float wh = ahi[it] ? fmaxf(E.x * uhi.x, E.y * uhi.y) : 0.f;
                sts32(stg1 + adst + (uint32)(it*8) * PITCH2, pack_f16x2(wl, wh));
            }
            CPA_WAIT0();
        }
        __syncthreads();
    }

    // ---- epilogue: ELU + store ----
    const int g = lane >> 2, cq = (lane & 3) * 2;
    #pragma unroll
    for (int mt = 0; mt < 2; mt++)
        #pragma unroll
        for (int nt = 0; nt < 8; nt++) {
            int i = i0 + iw + mt*16 + g;
            int o = ow + nt*8 + cq;
            float f0 = c[mt][nt][0], f1 = c[mt][nt][1];
            float f2 = c[mt][nt][2], f3 = c[mt][nt][3];
            f0 = f0 > 0.f ? f0 : expm1f(f0);
            f1 = f1 > 0.f ? f1 : expm1f(f1);
            f2 = f2 > 0.f ? f2 : expm1f(f2);
            f3 = f3 > 0.f ? f3 : expm1f(f3);
            *(float2*)&out[((size_t)(b*NN + i))   * FF + o] = make_float2(f0, f1);
            *(float2*)&out[((size_t)(b*NN + i+8)) * FF + o] = make_float2(f2, f3);
        }
}

extern "C" void kernel_launch(void* const* d_in, const int* in_sizes, int n_in,
                              void* d_out, int out_size)
{
    const float* x   = (const float*)d_in[0];
    const int*   adj = (const int*)d_in[1];
    const float* W   = (const float*)d_in[2];
    const float* a   = (const float*)d_in[3];
    float* out = (float*)d_out;

    cudaFuncSetAttribute(attgemm_mma, cudaFuncAttributeMaxDynamicSharedMemorySize, 2*STAGE);

    wsplit16_kernel<<<128, 256>>>(W);
    wa_kernel<<<32, 256>>>(W, a);
    sexp_kernel<<<2048, 256>>>(x);
    gemm1_f16<<<dim3(2, 128), 256>>>(x);
    zpass_kernel<<<dim3(2, 64, 8), 256>>>(adj);
    zreduce_kernel<<<64, 256>>>();
    attgemm_mma<<<dim3(32, 8), 256, 2*STAGE>>>(adj, out);
}

// round 9
// speedup vs baseline: 4.7579x; 1.1267x over previous
#include <cuda_runtime.h>
#include <cuda_fp16.h>

typedef unsigned int uint32;

#define BB 8
#define NN 2048
#define FF 256
#define M_TOT (BB*NN)   // 16384
#define PITCH 80        // gemm1 tile pitch (32 fp16 cols)
#define PITCH2 144      // attgemm tile pitch (64 fp16 cols)

// ---- scratch (device globals; no runtime allocations) ----
__device__ float g_E1[M_TOT], g_E1p[M_TOT], g_E2[M_TOT], g_E2p[M_TOT];
__device__ __align__(16) float g_wa1[FF], g_wa2[FF];
__device__ __align__(16) float g_Zp[64*M_TOT];             // 4 MB partials
__device__ __align__(16) float2 g_u2[M_TOT];               // (E2*invZ, E2p*invZ)
__device__ __align__(16) uint32 g_mask[64*M_TOT];          // adj bitmask [b][iword(64)][j]
// h^T fp16, [b][o][word]: word w of 16-group grp packs (j, j+8), j = grp*16 + (w&7)
__device__ __align__(16) unsigned int g_hT16[M_TOT*FF/2];  // 8 MB
__device__ __align__(16) unsigned int g_WT16[FF*FF/2];     // W^T fp16 [n][k-pairs]

// ================= helpers =================
__device__ __forceinline__ uint32 smem_u32(const void* p){
    uint32 a; asm("{ .reg .u64 t; cvta.to.shared.u64 t, %1; cvt.u32.u64 %0, t; }" : "=r"(a) : "l"(p));
    return a;
}
__device__ __forceinline__ uint32 pack_f16x2(float a, float b){
    uint32 r; asm("cvt.rn.f16x2.f32 %0, %1, %2;" : "=r"(r) : "f"(b), "f"(a)); return r;
}
__device__ __forceinline__ void sts32(uint32 addr, uint32 v){
    asm volatile("st.shared.b32 [%0], %1;" :: "r"(addr), "r"(v) : "memory");
}
__device__ __forceinline__ void sts64(uint32 addr, uint32 a, uint32 b){
    asm volatile("st.shared.v2.b32 [%0], {%1,%2};" :: "r"(addr), "r"(a), "r"(b) : "memory");
}
__device__ __forceinline__ void sts128(uint32 addr, uint4 v){
    asm volatile("st.shared.v4.b32 [%0], {%1,%2,%3,%4};"
        :: "r"(addr), "r"(v.x), "r"(v.y), "r"(v.z), "r"(v.w) : "memory");
}
__device__ __forceinline__ void ldm4(uint32* r, uint32 addr){
    asm volatile("ldmatrix.sync.aligned.m8n8.x4.shared.b16 {%0,%1,%2,%3}, [%4];"
        : "=r"(r[0]), "=r"(r[1]), "=r"(r[2]), "=r"(r[3]) : "r"(addr));
}
__device__ __forceinline__ void mma_f16(float* c, const uint32* a, uint32 b0, uint32 b1){
    asm volatile("mma.sync.aligned.m16n8k16.row.col.f32.f16.f16.f32 "
        "{%0,%1,%2,%3}, {%4,%5,%6,%7}, {%8,%9}, {%0,%1,%2,%3};"
        : "+f"(c[0]), "+f"(c[1]), "+f"(c[2]), "+f"(c[3])
        : "r"(a[0]), "r"(a[1]), "r"(a[2]), "r"(a[3]), "r"(b0), "r"(b1));
}
__device__ __forceinline__ void cpa16(uint32 dst, const void* src){
    asm volatile("cp.async.cg.shared.global [%0], [%1], 16;" :: "r"(dst), "l"(src) : "memory");
}
#define CPA_COMMIT() asm volatile("cp.async.commit_group;" ::: "memory")
#define CPA_WAIT0()  asm volatile("cp.async.wait_group 0;" ::: "memory")

// ============================================================
// wsplit16: W [k][n] fp32 -> W^T fp16 [n][k-pairs]
// ============================================================
__global__ void wsplit16_kernel(const float* __restrict__ W)
{
    int idx = blockIdx.x * 256 + threadIdx.x;
    int n = idx >> 7, kp = idx & 127;
    float v0 = W[(size_t)(2*kp)   * FF + n];
    float v1 = W[(size_t)(2*kp+1) * FF + n];
    g_WT16[n*128 + kp] = pack_f16x2(v0, v1);
}

// ============================================================
// wa: Wa1[k] = sum_n W[k][n]*a1[n] (fp32 exact path)
// ============================================================
__global__ void wa_kernel(const float* __restrict__ W, const float* __restrict__ a)
{
    int w = threadIdx.x >> 5, lane = threadIdx.x & 31;
    int k = blockIdx.x * 8 + w;
    float s1 = 0.f, s2 = 0.f;
    #pragma unroll
    for (int q = 0; q < 8; q++) {
        int e = lane + 32 * q;
        float v = __ldg(&W[(size_t)k * FF + e]);
        s1 += v * __ldg(&a[e]);
        s2 += v * __ldg(&a[256 + e]);
    }
    #pragma unroll
    for (int o = 16; o > 0; o >>= 1) {
        s1 += __shfl_xor_sync(0xffffffffu, s1, o);
        s2 += __shfl_xor_sync(0xffffffffu, s2, o);
    }
    if (lane == 0) { g_wa1[k] = s1; g_wa2[k] = s2; }
}

// ============================================================
// gemm1: h = x @ W fp16 HMMA, BM=64 x BN=256, reg double-buffer.
// Fused: s1/s2 row dots (fp32) + exp tables; hT16 direct from regs.
// grid (256 mtiles), 256 thr.
// ============================================================
__global__ __launch_bounds__(256,2) void gemm1_f16(const float* __restrict__ x)
{
    __shared__ __align__(16) unsigned char smA[64*PITCH];
    __shared__ __align__(16) unsigned char smB[256*PITCH];
    __shared__ float4 swa1[64], swa2[64];
    __shared__ float sred[2][64][8];
    const uint32 A = smem_u32(smA), B = smem_u32(smB);
    const int tid = threadIdx.x, lane = tid & 31, wid = tid >> 5;
    const int m0 = blockIdx.x * 64;
    const int iw = (wid & 1) * 32, ow = (wid >> 1) * 64;

    if (tid < 64)  swa1[tid] = ((const float4*)g_wa1)[tid & 63];
    else if (tid < 128) swa2[tid - 64] = ((const float4*)g_wa2)[tid - 64];

    float c[2][8][4];
    #pragma unroll
    for (int u = 0; u < 2; u++)
        #pragma unroll
        for (int v = 0; v < 8; v++)
            #pragma unroll
            for (int d = 0; d < 4; d++) c[u][v][d] = 0.f;

    // per-thread staging coords
    const int arow = tid >> 3, af4 = tid & 7;          // x: rows 0..31 (p0), +32 (p1)
    const uint4* wt = (const uint4*)g_WT16;
    float4 xa[2]; uint4 wb[4];
    float s1a[2] = {0.f, 0.f}, s2a[2] = {0.f, 0.f};

    // preload chunk 0
    #pragma unroll
    for (int p = 0; p < 2; p++)
        xa[p] = *(const float4*)&x[(size_t)(m0 + arow + p*32) * 256 + af4*4];
    #pragma unroll
    for (int p = 0; p < 4; p++) {
        int q = tid + p * 256;
        wb[p] = __ldg(&wt[(size_t)(q >> 2) * 32 + (q & 3)]);
    }
    __syncthreads();   // swa ready

    for (int kt = 0; kt < 256; kt += 32) {
        // stage regs -> smem (+ s accumulation)
        #pragma unroll
        for (int p = 0; p < 2; p++) {
            float4 v = xa[p];
            sts64(A + (uint32)(arow + p*32) * PITCH + af4 * 8,
                  pack_f16x2(v.x, v.y), pack_f16x2(v.z, v.w));
            float4 w1 = swa1[(kt >> 2) + af4];
            float4 w2 = swa2[(kt >> 2) + af4];
            s1a[p] += v.x*w1.x + v.y*w1.y + v.z*w1.z + v.w*w1.w;
            s2a[p] += v.x*w2.x + v.y*w2.y + v.z*w2.z + v.w*w2.w;
        }
        #pragma unroll
        for (int p = 0; p < 4; p++) {
            int q = tid + p * 256;
            sts128(B + (uint32)(q >> 2) * PITCH + (q & 3) * 16, wb[p]);
        }
        __syncthreads();
        // prefetch next chunk
        if (kt < 224) {
            #pragma unroll
            for (int p = 0; p < 2; p++)
                xa[p] = *(const float4*)&x[(size_t)(m0 + arow + p*32) * 256 + kt + 32 + af4*4];
            #pragma unroll
            for (int p = 0; p < 4; p++) {
                int q = tid + p * 256;
                wb[p] = __ldg(&wt[(size_t)(q >> 2) * 32 + ((kt + 32) >> 3) + (q & 3)]);
            }
        }
        // MMA
        const uint32 base_off = (uint32)(lane & 15) * PITCH + (uint32)(lane >> 4) * 16;
        #pragma unroll
        for (int ks = 0; ks < 2; ks++) {
            const uint32 off = base_off + ks * 32;
            uint32 A0[4], A1[4], Bt[4][4];
            ldm4(A0, A + (uint32)iw * PITCH + off);
            ldm4(A1, A + (uint32)(iw + 16) * PITCH + off);
            #pragma unroll
            for (int t = 0; t < 4; t++) ldm4(Bt[t], B + (uint32)(ow + t*16) * PITCH + off);
            #pragma unroll
            for (int t = 0; t < 4; t++) {
                mma_f16(c[0][t*2+0], A0, Bt[t][0], Bt[t][2]);
                mma_f16(c[1][t*2+0], A1, Bt[t][0], Bt[t][2]);
                mma_f16(c[0][t*2+1], A0, Bt[t][1], Bt[t][3]);
                mma_f16(c[1][t*2+1], A1, Bt[t][1], Bt[t][3]);
            }
        }
        __syncthreads();
    }

    // ---- s reduction + exp tables ----
    sred[0][arow][af4]      = s1a[0];
    sred[0][arow + 32][af4] = s1a[1];
    sred[1][arow][af4]      = s2a[0];
    sred[1][arow + 32][af4] = s2a[1];
    __syncthreads();
    if (tid < 128) {
        int which = tid >> 6, r = tid & 63;
        float s = 0.f;
        #pragma unroll
        for (int k2 = 0; k2 < 8; k2++) s += sred[which][r][k2];
        if (which == 0) {
            g_E1[m0 + r]  = __expf(s);
            g_E1p[m0 + r] = __expf(0.2f * s);
        } else {
            g_E2[m0 + r]  = __expf(s);
            g_E2p[m0 + r] = __expf(0.2f * s);
        }
    }

    // ---- hT16 epilogue: stride-8 pair packing direct from regs ----
    const int g = lane >> 2, cq = (lane & 3) * 2;
    const int bb = m0 >> 11;
    const int jb = (m0 & 2047) + iw;
    #pragma unroll
    for (int mt = 0; mt < 2; mt++) {
        uint32 pidx = (uint32)((jb + mt*16) >> 4) * 8 + g;
        #pragma unroll
        for (int nt = 0; nt < 8; nt++) {
            int n = ow + nt*8 + cq;
            g_hT16[((size_t)(bb*FF + n))   * 1024 + pidx] = pack_f16x2(c[mt][nt][0], c[mt][nt][2]);
            g_hT16[((size_t)(bb*FF + n+1)) * 1024 + pidx] = pack_f16x2(c[mt][nt][1], c[mt][nt][3]);
        }
    }
}

// ============================================================
// zpass: Z partials + adj bitmask emission (packed along i).
// grid (2 jchunk, 64 iseg, 8 b) = 1024 blocks, 256 thr, 4 j/thread
// ============================================================
__global__ __launch_bounds__(256) void zpass_kernel(const int* __restrict__ adj)
{
    __shared__ float2 sE[32];
    const int b = blockIdx.z, iseg = blockIdx.y, tid = threadIdx.x;
    const int j = blockIdx.x * 1024 + tid * 4;
    const int ibase = iseg * 32;
    if (tid < 32)
        sE[tid] = make_float2(g_E1[b*NN + ibase + tid], g_E1p[b*NN + ibase + tid]);
    __syncthreads();
    float e0 = __ldg(&g_E2[b*NN+j]),   e1 = __ldg(&g_E2[b*NN+j+1]);
    float e2 = __ldg(&g_E2[b*NN+j+2]), e3 = __ldg(&g_E2[b*NN+j+3]);
    float r0 = __ldg(&g_E2p[b*NN+j])   / e0, r1 = __ldg(&g_E2p[b*NN+j+1]) / e1;
    float r2 = __ldg(&g_E2p[b*NN+j+2]) / e2, r3 = __ldg(&g_E2p[b*NN+j+3]) / e3;
    const int4* ap = (const int4*)(adj + (size_t)(b*NN + ibase) * NN) + (j >> 2);
    float z0=0.f, z1=0.f, z2=0.f, z3=0.f;
    uint32 m0=0, m1=0, m2=0, m3=0;
    #pragma unroll 8
    for (int il = 0; il < 32; il++) {
        int4 av = __ldg(&ap[(size_t)il * (NN/4)]);
        float2 E = sE[il];
        float q0 = fmaxf(E.x, r0*E.y);
        float q1 = fmaxf(E.x, r1*E.y);
        float q2 = fmaxf(E.x, r2*E.y);
        float q3 = fmaxf(E.x, r3*E.y);
        m0 |= (uint32)av.x << il;     // adj values are exactly 0/1
        m1 |= (uint32)av.y << il;
        m2 |= (uint32)av.z << il;
        m3 |= (uint32)av.w << il;
        if (av.x) z0 += q0;
        if (av.y) z1 += q1;
        if (av.z) z2 += q2;
        if (av.w) z3 += q3;
    }
    *(float4*)&g_Zp[(size_t)iseg * M_TOT + b*NN + j] = make_float4(z0*e0, z1*e1, z2*e2, z3*e3);
    *(uint4*)&g_mask[(((size_t)b*64 + iseg)) * NN + j] = make_uint4(m0, m1, m2, m3);
}

__global__ void zreduce_kernel()
{
    int idx = blockIdx.x * 256 + threadIdx.x;
    float z = 0.f;
    #pragma unroll
    for (int s = 0; s < 64; s++) z += g_Zp[(size_t)s * M_TOT + idx];
    float iz = 1.0f / z;
    g_u2[idx] = make_float2(g_E2[idx] * iz, g_E2p[idx] * iz);
}

// ============================================================
// attgemm: fp16 single-pass, BJ=64. block = 64i x 256o, 256 thr,
// 2 CTA/SM. Bitmask adj (4 LDG/thread/chunk), cp.async B double-buffer.
// grid (32 itile, 8 b).
// ============================================================
#define ST_B   9216
#define STAGE  46080

__global__ __launch_bounds__(256,2) void attgemm_mma(float* __restrict__ out)
{
    extern __shared__ __align__(16) unsigned char dsm[];
    __shared__ float2 sE1[64];
    const uint32 sb = smem_u32(dsm);
    const int tid = threadIdx.x, lane = tid & 31, wid = tid >> 5;
    const int b = blockIdx.y, i0 = blockIdx.x * 64;
    const int iw = (wid & 1) * 32, ow = (wid >> 1) * 64;

    if (tid < 64)
        sE1[tid] = make_float2(g_E1[b*NN + i0 + tid], g_E1p[b*NN + i0 + tid]);

    float c[2][8][4];
    #pragma unroll
    for (int u = 0; u < 2; u++)
        #pragma unroll
        for (int v = 0; v < 8; v++)
            #pragma unroll
            for (int d = 0; d < 4; d++) c[u][v][d] = 0.f;

    // per-thread fixed coordinates
    const int jp   = tid & 31;                        // word col 0..31
    const int joff = ((jp >> 3) << 4) | (jp & 7);     // logical j offset (lo of pair)
    const int irow = tid >> 5;                        // 0..7; i = irow + it*8
    const uint32 adst = (uint32)irow * PITCH2 + jp * 4;
    const uint4* bbase = (const uint4*)g_hT16 + ((size_t)(b*FF + (tid >> 3))) * 256 + (tid & 7);
    const uint32 bd0 = ST_B + (uint32)(tid >> 3) * PITCH2 + (uint32)(tid & 7) * 16;
    const uint32* mbase = g_mask + ((size_t)b*64 + (i0 >> 5)) * NN + joff;
    const float2* u2b   = g_u2 + (size_t)b * NN + joff;

    uint32 c00, c01, c10, c11; float2 ulo, uhi;

    // ---- prologue: chunk 0 into buffer 0 ----
    {
        #pragma unroll
        for (int p = 0; p < 8; p++) cpa16(sb + bd0 + p*4608, bbase + p*8192);
        CPA_COMMIT();
        c00 = __ldg(&mbase[0]);       c01 = __ldg(&mbase[NN]);
        c10 = __ldg(&mbase[8]);       c11 = __ldg(&mbase[NN + 8]);
        ulo = __ldg(&u2b[0]);         uhi = __ldg(&u2b[8]);
        __syncthreads();                  // sE1 ready
        #pragma unroll
        for (int it = 0; it < 8; it++) {
            int i = irow + it*8;
            uint32 bl = ((it < 4 ? c00 : c01) >> (i & 31)) & 1;
            uint32 bh = ((it < 4 ? c10 : c11) >> (i & 31)) & 1;
            float2 E = sE1[i];
            float wl = bl ? fmaxf(E.x * ulo.x, E.y * ulo.y) : 0.f;
            float wh = bh ? fmaxf(E.x * uhi.x, E.y * uhi.y) : 0.f;
            sts32(sb + adst + (uint32)(it*8) * PITCH2, pack_f16x2(wl, wh));
        }
        CPA_WAIT0();
        __syncthreads();
    }

    for (int cc = 0; cc < 32; cc++) {
        const int s = cc & 1;
        const uint32 stg  = sb + (uint32)s * STAGE;
        const uint32 stg1 = sb + (uint32)(s ^ 1) * STAGE;
        if (cc < 31) {
            const int j1 = (cc + 1) * 64;
            #pragma unroll
            for (int p = 0; p < 8; p++) cpa16(stg1 + bd0 + p*4608, bbase + p*8192 + (j1 >> 3));
            CPA_COMMIT();
            c00 = __ldg(&mbase[j1]);      c01 = __ldg(&mbase[NN + j1]);
            c10 = __ldg(&mbase[j1 + 8]);  c11 = __ldg(&mbase[NN + j1 + 8]);
            ulo = __ldg(&u2b[j1]);        uhi = __ldg(&u2b[j1 + 8]);
        }
        // MMA over 64-wide chunk: 4 ks
        {
            const uint32 base_off = (uint32)(lane & 15) * PITCH2 + (uint32)(lane >> 4) * 16;
            #pragma unroll
            for (int ks = 0; ks < 4; ks++) {
                const uint32 off = base_off + ks * 32;
                uint32 A0[4], A1[4], Bt[4][4];
                ldm4(A0, stg + (uint32)iw * PITCH2 + off);
                ldm4(A1, stg + (uint32)(iw + 16) * PITCH2 + off);
                #pragma unroll
                for (int t = 0; t < 4; t++)
                    ldm4(Bt[t], stg + ST_B + (uint32)(ow + t*16) * PITCH2 + off);
                #pragma unroll
                for (int t = 0; t < 4; t++) {
                    mma_f16(c[0][t*2+0], A0, Bt[t][0], Bt[t][2]);
                    mma_f16(c[1][t*2+0], A1, Bt[t][0], Bt[t][2]);
                    mma_f16(c[0][t*2+1], A0, Bt[t][1], Bt[t][3]);
                    mma_f16(c[1][t*2+1], A1, Bt[t][1], Bt[t][3]);
                }
            }
        }
        if (cc < 31) {
            #pragma unroll
            for (int it = 0; it < 8; it++) {
                int i = irow + it*8;
                uint32 bl = ((it < 4 ? c00 : c01) >> (i & 31)) & 1;
                uint32 bh = ((it < 4 ? c10 : c11) >> (i & 31)) & 1;
                float2 E = sE1[i];
                float wl = bl ? fmaxf(E.x * ulo.x, E.y * ulo.y) : 0.f;
                float wh = bh ? fmaxf(E.x * uhi.x, E.y * uhi.y) : 0.f;
                sts32(stg1 + adst + (uint32)(it*8) * PITCH2, pack_f16x2(wl, wh));
            }
            CPA_WAIT0();
        }
        __syncthreads();
    }

    // ---- epilogue: ELU + store ----
    const int g = lane >> 2, cq = (lane & 3) * 2;
    #pragma unroll
    for (int mt = 0; mt < 2; mt++)
        #pragma unroll
        for (int nt = 0; nt < 8; nt++) {
            int i = i0 + iw + mt*16 + g;
            int o = ow + nt*8 + cq;
            float f0 = c[mt][nt][0], f1 = c[mt][nt][1];
            float f2 = c[mt][nt][2], f3 = c[mt][nt][3];
            f0 = f0 > 0.f ? f0 : expm1f(f0);
            f1 = f1 > 0.f ? f1 : expm1f(f1);
            f2 = f2 > 0.f ? f2 : expm1f(f2);
            f3 = f3 > 0.f ? f3 : expm1f(f3);
            *(float2*)&out[((size_t)(b*NN + i))   * FF + o] = make_float2(f0, f1);
            *(float2*)&out[((size_t)(b*NN + i+8)) * FF + o] = make_float2(f2, f3);
        }
}

extern "C" void kernel_launch(void* const* d_in, const int* in_sizes, int n_in,
                              void* d_out, int out_size)
{
    const float* x   = (const float*)d_in[0];
    const int*   adj = (const int*)d_in[1];
    const float* W   = (const float*)d_in[2];
    const float* a   = (const float*)d_in[3];
    float* out = (float*)d_out;

    cudaFuncSetAttribute(attgemm_mma, cudaFuncAttributeMaxDynamicSharedMemorySize, 2*STAGE);

    wsplit16_kernel<<<128, 256>>>(W);
    wa_kernel<<<32, 256>>>(W, a);
    gemm1_f16<<<256, 256>>>(x);
    zpass_kernel<<<dim3(2, 64, 8), 256>>>(adj);
    zreduce_kernel<<<64, 256>>>();
    attgemm_mma<<<dim3(32, 8), 256, 2*STAGE>>>(out);
}